// round 8
// baseline (speedup 1.0000x reference)
#include <cuda_runtime.h>
#include <math.h>

#define B_    64
#define T_    128
#define IN_   64
#define TE_   256
#define H_    512
#define A_    256
#define OUT_  64
#define G4_   2048
#define KIN_  1088
#define GRID_ 128

__device__ float g_keys [B_*TE_*A_];
__device__ float g_keysT[B_*A_*TE_];
__device__ float g_Wp  [G4_*KIN_];
__device__ float g_bias[G4_];
__device__ float g_inp [B_*KIN_];
__device__ float g_h   [B_*H_];
__device__ float g_qp  [4*B_*A_];
__device__ float g_part[4*B_*G4_];
__device__ float g_hist[B_*T_*H_];
__device__ unsigned g_bar;

__device__ __forceinline__ float sigf(float xx) {
    return 1.0f / (1.0f + __expf(-xx));
}
__device__ __forceinline__ float tanha(float xx) {
    float y;
    asm("tanh.approx.f32 %0, %1;" : "=f"(y) : "f"(xx));
    return y;
}

// R4 barrier with the single change: no __nanosleep in the spin
__device__ __forceinline__ void gbar(unsigned& ep) {
    ep += GRID_;
    __syncthreads();
    if (threadIdx.x == 0) {
        __threadfence();
        atomicAdd(&g_bar, 1u);
        volatile unsigned* p = &g_bar;
        while (*p < ep) { }
        __threadfence();
    }
    __syncthreads();
}

__device__ __forceinline__ float blk_reduce_max(float vv, float* red) {
#pragma unroll
    for (int o = 16; o > 0; o >>= 1)
        vv = fmaxf(vv, __shfl_xor_sync(0xffffffffu, vv, o));
    if ((threadIdx.x & 31) == 0) red[threadIdx.x >> 5] = vv;
    __syncthreads();
    if (threadIdx.x == 0) {
        float mm = red[0];
#pragma unroll
        for (int i = 1; i < 8; i++) mm = fmaxf(mm, red[i]);
        red[0] = mm;
    }
    __syncthreads();
    float r = red[0];
    __syncthreads();
    return r;
}
__device__ __forceinline__ float blk_reduce_sum(float vv, float* red) {
#pragma unroll
    for (int o = 16; o > 0; o >>= 1)
        vv += __shfl_xor_sync(0xffffffffu, vv, o);
    if ((threadIdx.x & 31) == 0) red[threadIdx.x >> 5] = vv;
    __syncthreads();
    if (threadIdx.x == 0) {
        float ss = red[0];
#pragma unroll
        for (int i = 1; i < 8; i++) ss += red[i];
        red[0] = ss;
    }
    __syncthreads();
    float r = red[0];
    __syncthreads();
    return r;
}

// 64x64xK tile GEMM: C = A(64,K) * B(64,K)^T, smem double-buffered, 4x4/thread.
template<bool CG>
__device__ __forceinline__ void tile_gemm64(
    const float* __restrict__ Ag, int lda,
    const float* __restrict__ Bg, int ldb,
    int nc, float* S, float acc[4][4])
{
    float (*As)[16][68] = (float(*)[16][68])S;
    float (*Bs)[16][68] = (float(*)[16][68])(S + 2176);
    const int tid = threadIdx.x;
    const int lrow = tid >> 2, lk = (tid & 3) << 2;
    const int tm = (tid & 15) << 2, tn = (tid >> 4) << 2;
    Ag += (size_t)lrow * lda + lk;
    Bg += (size_t)lrow * ldb + lk;
#pragma unroll
    for (int i = 0; i < 4; i++)
#pragma unroll
        for (int j = 0; j < 4; j++) acc[i][j] = 0.f;

    float4 ra = CG ? __ldcg((const float4*)Ag) : *(const float4*)Ag;
    float4 rb = *(const float4*)Bg;
    int buf = 0;
    As[0][lk + 0][lrow] = ra.x; As[0][lk + 1][lrow] = ra.y;
    As[0][lk + 2][lrow] = ra.z; As[0][lk + 3][lrow] = ra.w;
    Bs[0][lk + 0][lrow] = rb.x; Bs[0][lk + 1][lrow] = rb.y;
    Bs[0][lk + 2][lrow] = rb.z; Bs[0][lk + 3][lrow] = rb.w;
    __syncthreads();

    for (int c = 0; c < nc; c++) {
        if (c + 1 < nc) {
            const float4* ap = (const float4*)(Ag + (c + 1) * 16);
            ra = CG ? __ldcg(ap) : *ap;
            rb = *(const float4*)(Bg + (c + 1) * 16);
        }
#pragma unroll
        for (int kk = 0; kk < 16; kk++) {
            float4 av = *(const float4*)&As[buf][kk][tm];
            float4 bv = *(const float4*)&Bs[buf][kk][tn];
            acc[0][0] += av.x * bv.x; acc[0][1] += av.x * bv.y;
            acc[0][2] += av.x * bv.z; acc[0][3] += av.x * bv.w;
            acc[1][0] += av.y * bv.x; acc[1][1] += av.y * bv.y;
            acc[1][2] += av.y * bv.z; acc[1][3] += av.y * bv.w;
            acc[2][0] += av.z * bv.x; acc[2][1] += av.z * bv.y;
            acc[2][2] += av.z * bv.z; acc[2][3] += av.z * bv.w;
            acc[3][0] += av.w * bv.x; acc[3][1] += av.w * bv.y;
            acc[3][2] += av.w * bv.z; acc[3][3] += av.w * bv.w;
        }
        __syncthreads();
        if (c + 1 < nc) {
            buf ^= 1;
            As[buf][lk + 0][lrow] = ra.x; As[buf][lk + 1][lrow] = ra.y;
            As[buf][lk + 2][lrow] = ra.z; As[buf][lk + 3][lrow] = ra.w;
            Bs[buf][lk + 0][lrow] = rb.x; Bs[buf][lk + 1][lrow] = rb.y;
            Bs[buf][lk + 2][lrow] = rb.z; Bs[buf][lk + 3][lrow] = rb.w;
            __syncthreads();
        }
    }
}

// ---------------- prologue / epilogue kernels ----------------
__global__ void reset_kernel() {
    if (threadIdx.x == 0 && blockIdx.x == 0) g_bar = 0u;
}

__global__ void __launch_bounds__(256) pack_kernel(
    const float* __restrict__ Wih, const float* __restrict__ Whh,
    const float* __restrict__ bih, const float* __restrict__ bhh)
{
    int i = blockIdx.x * 256 + threadIdx.x;
    int s = gridDim.x * 256;
    for (int j = i; j < G4_ * KIN_; j += s) {
        int n = j / KIN_, k = j % KIN_;
        g_Wp[j] = (k < 576) ? Wih[(size_t)n * 576 + k]
                            : Whh[(size_t)n * H_ + (k - 576)];
    }
    for (int j = i; j < G4_; j += s) g_bias[j] = bih[j] + bhh[j];
}

__global__ void transpose_kernel() {
    __shared__ float tile[32][33];
    int b = blockIdx.z;
    int e0 = blockIdx.x * 32, a0 = blockIdx.y * 32;
    const float* src = g_keys + ((size_t)b * TE_ + e0) * A_ + a0;
    for (int r = threadIdx.y; r < 32; r += 8)
        tile[r][threadIdx.x] = src[(size_t)r * A_ + threadIdx.x];
    __syncthreads();
    float* dst = g_keysT + ((size_t)b * A_ + a0) * TE_ + e0;
    for (int r = threadIdx.y; r < 32; r += 8)
        dst[(size_t)r * TE_ + threadIdx.x] = tile[threadIdx.x][r];
}

__global__ void __launch_bounds__(256) gemm_abt_kernel(
    const float* __restrict__ Am, const float* __restrict__ Bm,
    float* __restrict__ Cm, int N, int K, const float* __restrict__ bias)
{
    __shared__ float S[4352];
    float acc[4][4];
    const int m0 = blockIdx.x * 64, n0 = blockIdx.y * 64;
    tile_gemm64<false>(Am + (size_t)m0 * K, K, Bm + (size_t)n0 * K, K, K >> 4, S, acc);
    const int tid = threadIdx.x;
    const int tm = (tid & 15) << 2, tn = (tid >> 4) << 2;
    float b0 = 0.f, b1 = 0.f, b2 = 0.f, b3 = 0.f;
    if (bias) {
        b0 = bias[n0 + tn + 0]; b1 = bias[n0 + tn + 1];
        b2 = bias[n0 + tn + 2]; b3 = bias[n0 + tn + 3];
    }
#pragma unroll
    for (int i = 0; i < 4; i++) {
        float4 o;
        o.x = acc[i][0] + b0; o.y = acc[i][1] + b1;
        o.z = acc[i][2] + b2; o.w = acc[i][3] + b3;
        *(float4*)&Cm[(size_t)(m0 + tm + i) * N + n0 + tn] = o;
    }
}

// ---------------- persistent decoder (Round-4 structure, 4 barriers) --------
__global__ void __launch_bounds__(256, 1) persist_kernel(
    const float* __restrict__ x, const float* __restrict__ enc,
    const float* __restrict__ Wq, const float* __restrict__ v)
{
    __shared__ float S[4352];
    __shared__ float sq[A_], sv[A_], sw[TE_], sred[8];
    __shared__ float4 sctx[256];
    const int tid = threadIdx.x, bid = blockIdx.x;
    unsigned ep = 0;
    const int b0 = bid >> 1, hf = bid & 1;
    const int u0 = hf * 256 + tid;
    float c_reg = 0.f;

    if (bid < 64) {
        for (int u = tid; u < H_; u += 256) g_h[(size_t)bid*H_ + u] = 0.f;
        if (tid < 128) g_inp[(size_t)bid*KIN_ + IN_ + H_ + tid + 384] = 0.f;
        for (int u = tid; u < H_; u += 256) g_inp[(size_t)bid*KIN_ + 576 + u] = 0.f;
        sv[tid] = v[tid];
    }
    gbar(ep);

    for (int t = 0; t < T_; t++) {
        // P1: q partials (16 CTAs): q[b][a] over k-split of 4
        if (bid < 16) {
            const int nt = bid & 3, ks = bid >> 2;
            float acc[4][4];
            tile_gemm64<true>(g_h + ks * 128, H_,
                              Wq + (size_t)(nt * 64) * H_ + ks * 128, H_, 8, S, acc);
            const int tm = (tid & 15) << 2, tn = (tid >> 4) << 2;
            float* C = g_qp + ks * (B_ * A_);
#pragma unroll
            for (int i = 0; i < 4; i++) {
                float4 o = {acc[i][0], acc[i][1], acc[i][2], acc[i][3]};
                *(float4*)&C[(tm + i) * A_ + nt * 64 + tn] = o;
            }
        }
        gbar(ep);

        // P2: attention, one CTA per b (64 CTAs)
        if (bid < 64) {
            const int b = bid;
            sq[tid] = __ldcg(&g_qp[b * A_ + tid])
                    + __ldcg(&g_qp[B_ * A_ + b * A_ + tid])
                    + __ldcg(&g_qp[2 * B_ * A_ + b * A_ + tid])
                    + __ldcg(&g_qp[3 * B_ * A_ + b * A_ + tid]);
            __syncthreads();
            float e = 0.f;
            const float* kp = g_keysT + ((size_t)b * A_) * TE_ + tid;
#pragma unroll 8
            for (int a = 0; a < A_; a++)
                e += sv[a] * tanha(sq[a] + kp[(size_t)a * TE_]);
            float mx = blk_reduce_max(e, sred);
            float wv = __expf(e - mx);
            float sm = blk_reduce_sum(wv, sred);
            sw[tid] = wv * __fdividef(1.f, sm);
            if (tid < IN_)
                g_inp[b * KIN_ + tid] = x[((size_t)b * T_ + t) * IN_ + tid];
            __syncthreads();
            const int d4 = tid & 127, th = tid >> 7;
            float4 acc = {0.f, 0.f, 0.f, 0.f};
            const float4* ebase = (const float4*)(enc + (size_t)b * TE_ * H_) + d4;
#pragma unroll 4
            for (int e2 = th*128; e2 < th*128 + 128; e2++) {
                float ww = sw[e2];
                float4 ev = ebase[(size_t)e2 * (H_/4)];
                acc.x += ww*ev.x; acc.y += ww*ev.y;
                acc.z += ww*ev.z; acc.w += ww*ev.w;
            }
            sctx[tid] = acc;
            __syncthreads();
            if (tid < 128) {
                float4 a0 = sctx[tid], a1 = sctx[128 + tid];
                float4 o = {a0.x + a1.x, a0.y + a1.y, a0.z + a1.z, a0.w + a1.w};
                *(float4*)&g_inp[b * KIN_ + IN_ + tid * 4] = o;
            }
        }
        gbar(ep);

        // P5: gates GEMM partials (all 128 CTAs)
        {
            const int nt = bid >> 2, ks = bid & 3;
            float acc[4][4];
            tile_gemm64<true>(g_inp + ks * 272, KIN_,
                              g_Wp + (size_t)(nt * 64) * KIN_ + ks * 272, KIN_, 17, S, acc);
            const int tm = (tid & 15) << 2, tn = (tid >> 4) << 2;
            float* C = g_part + (size_t)ks * (B_ * G4_);
#pragma unroll
            for (int i = 0; i < 4; i++) {
                float4 o = {acc[i][0], acc[i][1], acc[i][2], acc[i][3]};
                *(float4*)&C[(size_t)(tm + i) * G4_ + nt * 64 + tn] = o;
            }
        }
        gbar(ep);

        // P0: combine partials + LSTM cell; c in registers; unit u0 of batch b0
        {
            float gi = g_bias[u0], gf = g_bias[H_ + u0];
            float gg = g_bias[2 * H_ + u0], go = g_bias[3 * H_ + u0];
#pragma unroll
            for (int p = 0; p < 4; p++) {
                const float* pp = g_part + (size_t)p * (B_ * G4_) + b0 * G4_;
                gi += __ldcg(&pp[u0]);
                gf += __ldcg(&pp[H_ + u0]);
                gg += __ldcg(&pp[2 * H_ + u0]);
                go += __ldcg(&pp[3 * H_ + u0]);
            }
            float cn = sigf(gf) * c_reg + sigf(gi) * tanhf(gg);
            float hn = sigf(go) * tanhf(cn);
            c_reg = cn;
            g_h[(size_t)b0 * H_ + u0] = hn;
            g_inp[(size_t)b0 * KIN_ + 576 + u0] = hn;
            g_hist[((size_t)b0 * T_ + t) * H_ + u0] = hn;
        }
        gbar(ep);
    }
}

// ---------------------------------------------------------------------------
extern "C" void kernel_launch(void* const* d_in, const int* in_sizes, int n_in,
                              void* d_out, int out_size)
{
    const float* x   = (const float*)d_in[0];
    const float* enc = (const float*)d_in[1];
    const float* Wq  = (const float*)d_in[2];
    const float* Wk  = (const float*)d_in[3];
    const float* v   = (const float*)d_in[4];
    const float* Wih = (const float*)d_in[5];
    const float* Whh = (const float*)d_in[6];
    const float* bih = (const float*)d_in[7];
    const float* bhh = (const float*)d_in[8];
    const float* Wfc = (const float*)d_in[9];
    const float* bfc = (const float*)d_in[10];

    float* keys_p = nullptr;
    float* hist_p = nullptr;
    cudaGetSymbolAddress((void**)&keys_p, g_keys);
    cudaGetSymbolAddress((void**)&hist_p, g_hist);

    dim3 thr(256);

    reset_kernel<<<1, 32>>>();
    pack_kernel<<<512, thr>>>(Wih, Whh, bih, bhh);

    // keys[b,e,a] = enc[b,e,:] . W_key[a,:] ; then transpose to [b][a][e]
    gemm_abt_kernel<<<dim3((B_*TE_)/64, A_/64), thr>>>(enc, Wk, keys_p, A_, H_, nullptr);
    transpose_kernel<<<dim3(TE_/32, A_/32, B_), dim3(32, 8)>>>();

    persist_kernel<<<GRID_, thr>>>(x, enc, Wq, v);

    // out[b,t,:] = h_hist[b,t,:] @ Wfc^T + bfc
    gemm_abt_kernel<<<dim3((B_*T_)/64, OUT_/64), thr>>>(hist_p, Wfc, (float*)d_out, OUT_, H_, bfc);
}

// round 9
// speedup vs baseline: 1.1550x; 1.1550x over previous
#include <cuda_runtime.h>
#include <math.h>

#define B_    64
#define T_    128
#define IN_   64
#define TE_   256
#define H_    512
#define A_    256
#define OUT_  64
#define G4_   2048
#define KIN_  1088
#define GRID_ 128

__device__ float g_keys [B_*TE_*A_];
__device__ float g_keysT[B_*A_*TE_];
__device__ float g_WqT [H_*A_];            // [k][a]
__device__ float g_Wp  [G4_*KIN_];
__device__ float g_bias[G4_];
__device__ float g_inp [B_*KIN_];
__device__ float g_h   [B_*H_];
__device__ float g_qp  [2*B_*A_];          // q partials: [hf][b][a]
__device__ float g_part[4*B_*G4_];
__device__ float g_hist[B_*T_*H_];
__device__ unsigned g_bar;

__device__ __forceinline__ float sigf(float xx) {
    return 1.0f / (1.0f + __expf(-xx));
}
__device__ __forceinline__ float tanha(float xx) {
    float y;
    asm("tanh.approx.f32 %0, %1;" : "=f"(y) : "f"(xx));
    return y;
}

// R4-proven barrier: nanosleep backoff spin
__device__ __forceinline__ void gbar(unsigned& ep) {
    ep += GRID_;
    __syncthreads();
    if (threadIdx.x == 0) {
        __threadfence();
        atomicAdd(&g_bar, 1u);
        volatile unsigned* p = &g_bar;
        while (*p < ep) __nanosleep(32);
        __threadfence();
    }
    __syncthreads();
}

__device__ __forceinline__ float blk_reduce_max(float vv, float* red) {
#pragma unroll
    for (int o = 16; o > 0; o >>= 1)
        vv = fmaxf(vv, __shfl_xor_sync(0xffffffffu, vv, o));
    if ((threadIdx.x & 31) == 0) red[threadIdx.x >> 5] = vv;
    __syncthreads();
    if (threadIdx.x == 0) {
        float mm = red[0];
#pragma unroll
        for (int i = 1; i < 8; i++) mm = fmaxf(mm, red[i]);
        red[0] = mm;
    }
    __syncthreads();
    float r = red[0];
    __syncthreads();
    return r;
}
__device__ __forceinline__ float blk_reduce_sum(float vv, float* red) {
#pragma unroll
    for (int o = 16; o > 0; o >>= 1)
        vv += __shfl_xor_sync(0xffffffffu, vv, o);
    if ((threadIdx.x & 31) == 0) red[threadIdx.x >> 5] = vv;
    __syncthreads();
    if (threadIdx.x == 0) {
        float ss = red[0];
#pragma unroll
        for (int i = 1; i < 8; i++) ss += red[i];
        red[0] = ss;
    }
    __syncthreads();
    float r = red[0];
    __syncthreads();
    return r;
}

// 64x64xK tile GEMM: C = A(64,K) * B(64,K)^T, smem double-buffered, 4x4/thread.
template<bool CG>
__device__ __forceinline__ void tile_gemm64(
    const float* __restrict__ Ag, int lda,
    const float* __restrict__ Bg, int ldb,
    int nc, float* S, float acc[4][4])
{
    float (*As)[16][68] = (float(*)[16][68])S;
    float (*Bs)[16][68] = (float(*)[16][68])(S + 2176);
    const int tid = threadIdx.x;
    const int lrow = tid >> 2, lk = (tid & 3) << 2;
    const int tm = (tid & 15) << 2, tn = (tid >> 4) << 2;
    Ag += (size_t)lrow * lda + lk;
    Bg += (size_t)lrow * ldb + lk;
#pragma unroll
    for (int i = 0; i < 4; i++)
#pragma unroll
        for (int j = 0; j < 4; j++) acc[i][j] = 0.f;

    float4 ra = CG ? __ldcg((const float4*)Ag) : *(const float4*)Ag;
    float4 rb = *(const float4*)Bg;
    int buf = 0;
    As[0][lk + 0][lrow] = ra.x; As[0][lk + 1][lrow] = ra.y;
    As[0][lk + 2][lrow] = ra.z; As[0][lk + 3][lrow] = ra.w;
    Bs[0][lk + 0][lrow] = rb.x; Bs[0][lk + 1][lrow] = rb.y;
    Bs[0][lk + 2][lrow] = rb.z; Bs[0][lk + 3][lrow] = rb.w;
    __syncthreads();

    for (int c = 0; c < nc; c++) {
        if (c + 1 < nc) {
            const float4* ap = (const float4*)(Ag + (c + 1) * 16);
            ra = CG ? __ldcg(ap) : *ap;
            rb = *(const float4*)(Bg + (c + 1) * 16);
        }
#pragma unroll
        for (int kk = 0; kk < 16; kk++) {
            float4 av = *(const float4*)&As[buf][kk][tm];
            float4 bv = *(const float4*)&Bs[buf][kk][tn];
            acc[0][0] += av.x * bv.x; acc[0][1] += av.x * bv.y;
            acc[0][2] += av.x * bv.z; acc[0][3] += av.x * bv.w;
            acc[1][0] += av.y * bv.x; acc[1][1] += av.y * bv.y;
            acc[1][2] += av.y * bv.z; acc[1][3] += av.y * bv.w;
            acc[2][0] += av.z * bv.x; acc[2][1] += av.z * bv.y;
            acc[2][2] += av.z * bv.z; acc[2][3] += av.z * bv.w;
            acc[3][0] += av.w * bv.x; acc[3][1] += av.w * bv.y;
            acc[3][2] += av.w * bv.z; acc[3][3] += av.w * bv.w;
        }
        __syncthreads();
        if (c + 1 < nc) {
            buf ^= 1;
            As[buf][lk + 0][lrow] = ra.x; As[buf][lk + 1][lrow] = ra.y;
            As[buf][lk + 2][lrow] = ra.z; As[buf][lk + 3][lrow] = ra.w;
            Bs[buf][lk + 0][lrow] = rb.x; Bs[buf][lk + 1][lrow] = rb.y;
            Bs[buf][lk + 2][lrow] = rb.z; Bs[buf][lk + 3][lrow] = rb.w;
            __syncthreads();
        }
    }
}

// ---------------- prologue / epilogue kernels ----------------
__global__ void reset_kernel() {
    if (threadIdx.x == 0 && blockIdx.x == 0) g_bar = 0u;
}

__global__ void __launch_bounds__(256) pack_kernel(
    const float* __restrict__ Wq, const float* __restrict__ Wih,
    const float* __restrict__ Whh, const float* __restrict__ bih,
    const float* __restrict__ bhh)
{
    int i = blockIdx.x * 256 + threadIdx.x;
    int s = gridDim.x * 256;
    for (int j = i; j < G4_ * KIN_; j += s) {
        int n = j / KIN_, k = j % KIN_;
        g_Wp[j] = (k < 576) ? Wih[(size_t)n * 576 + k]
                            : Whh[(size_t)n * H_ + (k - 576)];
    }
    for (int j = i; j < G4_; j += s) g_bias[j] = bih[j] + bhh[j];
    for (int j = i; j < H_ * A_; j += s) {
        int k = j / A_, a = j % A_;
        g_WqT[j] = Wq[(size_t)a * H_ + k];
    }
}

__global__ void transpose_kernel() {
    __shared__ float tile[32][33];
    int b = blockIdx.z;
    int e0 = blockIdx.x * 32, a0 = blockIdx.y * 32;
    const float* src = g_keys + ((size_t)b * TE_ + e0) * A_ + a0;
    for (int r = threadIdx.y; r < 32; r += 8)
        tile[r][threadIdx.x] = src[(size_t)r * A_ + threadIdx.x];
    __syncthreads();
    float* dst = g_keysT + ((size_t)b * A_ + a0) * TE_ + e0;
    for (int r = threadIdx.y; r < 32; r += 8)
        dst[(size_t)r * TE_ + threadIdx.x] = tile[threadIdx.x][r];
}

__global__ void __launch_bounds__(256) gemm_abt_kernel(
    const float* __restrict__ Am, const float* __restrict__ Bm,
    float* __restrict__ Cm, int N, int K, const float* __restrict__ bias)
{
    __shared__ float S[4352];
    float acc[4][4];
    const int m0 = blockIdx.x * 64, n0 = blockIdx.y * 64;
    tile_gemm64<false>(Am + (size_t)m0 * K, K, Bm + (size_t)n0 * K, K, K >> 4, S, acc);
    const int tid = threadIdx.x;
    const int tm = (tid & 15) << 2, tn = (tid >> 4) << 2;
    float b0 = 0.f, b1 = 0.f, b2 = 0.f, b3 = 0.f;
    if (bias) {
        b0 = bias[n0 + tn + 0]; b1 = bias[n0 + tn + 1];
        b2 = bias[n0 + tn + 2]; b3 = bias[n0 + tn + 3];
    }
#pragma unroll
    for (int i = 0; i < 4; i++) {
        float4 o;
        o.x = acc[i][0] + b0; o.y = acc[i][1] + b1;
        o.z = acc[i][2] + b2; o.w = acc[i][3] + b3;
        *(float4*)&Cm[(size_t)(m0 + tm + i) * N + n0 + tn] = o;
    }
}

// ---------------- persistent decoder: 3 barriers/step ----------------
__global__ void __launch_bounds__(256, 1) persist_kernel(
    const float* __restrict__ x, const float* __restrict__ enc,
    const float* __restrict__ v)
{
    __shared__ float S[4352];
    __shared__ float sq[A_], sv[A_], sw[TE_], sred[8];
    __shared__ float h_loc[256];
    __shared__ float4 sctx[256];
    const int tid = threadIdx.x, bid = blockIdx.x;
    unsigned ep = 0;
    const int b0 = bid >> 1, hf = bid & 1;
    const int u0 = hf * 256 + tid;
    float c_reg = 0.f;

    // init: h(-1)=0, q-partials(t=0)=0
    if (bid < 64) {
        for (int u = tid; u < H_; u += 256) {
            g_h[(size_t)bid * H_ + u] = 0.f;
            g_inp[(size_t)bid * KIN_ + 576 + u] = 0.f;
        }
        sv[tid] = v[tid];
    }
    g_qp[bid * 256 + tid] = 0.f;      // 128*256 = 2*B*A exactly
    gbar(ep);

    for (int t = 0; t < T_; t++) {
        // ======== P2: attention, one CTA per b (64 CTAs) ========
        if (bid < 64) {
            const int b = bid;
            sq[tid] = __ldcg(&g_qp[b * A_ + tid])
                    + __ldcg(&g_qp[B_ * A_ + b * A_ + tid]);
            __syncthreads();
            float e = 0.f;
            const float* kp = g_keysT + ((size_t)b * A_) * TE_ + tid;
#pragma unroll 8
            for (int a = 0; a < A_; a++)
                e += sv[a] * tanha(sq[a] + kp[(size_t)a * TE_]);
            float mx = blk_reduce_max(e, sred);
            float wv = __expf(e - mx);
            float sm = blk_reduce_sum(wv, sred);
            sw[tid] = wv * __fdividef(1.f, sm);
            if (tid < IN_)
                g_inp[b * KIN_ + tid] = x[((size_t)b * T_ + t) * IN_ + tid];
            __syncthreads();
            const int d4 = tid & 127, th = tid >> 7;
            float4 acc = {0.f, 0.f, 0.f, 0.f};
            const float4* ebase = (const float4*)(enc + (size_t)b * TE_ * H_) + d4;
#pragma unroll 4
            for (int e2 = th*128; e2 < th*128 + 128; e2++) {
                float ww = sw[e2];
                float4 ev = ebase[(size_t)e2 * (H_/4)];
                acc.x += ww*ev.x; acc.y += ww*ev.y;
                acc.z += ww*ev.z; acc.w += ww*ev.w;
            }
            sctx[tid] = acc;
            __syncthreads();
            if (tid < 128) {
                float4 a0 = sctx[tid], a1 = sctx[128 + tid];
                float4 o = {a0.x + a1.x, a0.y + a1.y, a0.z + a1.z, a0.w + a1.w};
                *(float4*)&g_inp[b * KIN_ + IN_ + tid * 4] = o;
            }
        }
        gbar(ep);

        // ======== P5: gates GEMM partials (all 128 CTAs) ========
        {
            const int nt = bid >> 2, ks = bid & 3;
            float acc[4][4];
            tile_gemm64<true>(g_inp + ks * 272, KIN_,
                              g_Wp + (size_t)(nt * 64) * KIN_ + ks * 272, KIN_, 17, S, acc);
            const int tm = (tid & 15) << 2, tn = (tid >> 4) << 2;
            float* C = g_part + (size_t)ks * (B_ * G4_);
#pragma unroll
            for (int i = 0; i < 4; i++) {
                float4 o = {acc[i][0], acc[i][1], acc[i][2], acc[i][3]};
                *(float4*)&C[(size_t)(tm + i) * G4_ + nt * 64 + tn] = o;
            }
        }
        gbar(ep);

        // ======== P0: combine + LSTM cell + q-partial for next step ========
        {
            float gi = g_bias[u0], gf = g_bias[H_ + u0];
            float gg = g_bias[2 * H_ + u0], go = g_bias[3 * H_ + u0];
#pragma unroll
            for (int p = 0; p < 4; p++) {
                const float* pp = g_part + (size_t)p * (B_ * G4_) + b0 * G4_;
                gi += __ldcg(&pp[u0]);
                gf += __ldcg(&pp[H_ + u0]);
                gg += __ldcg(&pp[2 * H_ + u0]);
                go += __ldcg(&pp[3 * H_ + u0]);
            }
            float cn = sigf(gf) * c_reg + sigf(gi) * tanhf(gg);
            float hn = sigf(go) * tanhf(cn);
            c_reg = cn;
            g_h[(size_t)b0 * H_ + u0] = hn;
            g_inp[(size_t)b0 * KIN_ + 576 + u0] = hn;
            g_hist[((size_t)b0 * T_ + t) * H_ + u0] = hn;
            h_loc[tid] = hn;
        }
        __syncthreads();
        // q-partial for step t+1: a = tid; sum over this CTA's 256 h-units.
        // WqT rows are broadcast per j (all threads same row), coalesced over a.
        {
            float qa = 0.f;
            const float* wt = g_WqT + (size_t)(hf * 256) * A_ + tid;
#pragma unroll 8
            for (int j = 0; j < 256; j++)
                qa += h_loc[j] * wt[(size_t)j * A_];
            g_qp[(size_t)hf * (B_ * A_) + b0 * A_ + tid] = qa;
        }
        gbar(ep);
    }
}

// ---------------------------------------------------------------------------
extern "C" void kernel_launch(void* const* d_in, const int* in_sizes, int n_in,
                              void* d_out, int out_size)
{
    const float* x   = (const float*)d_in[0];
    const float* enc = (const float*)d_in[1];
    const float* Wq  = (const float*)d_in[2];
    const float* Wk  = (const float*)d_in[3];
    const float* v   = (const float*)d_in[4];
    const float* Wih = (const float*)d_in[5];
    const float* Whh = (const float*)d_in[6];
    const float* bih = (const float*)d_in[7];
    const float* bhh = (const float*)d_in[8];
    const float* Wfc = (const float*)d_in[9];
    const float* bfc = (const float*)d_in[10];

    float* keys_p = nullptr;
    float* hist_p = nullptr;
    cudaGetSymbolAddress((void**)&keys_p, g_keys);
    cudaGetSymbolAddress((void**)&hist_p, g_hist);

    dim3 thr(256);

    reset_kernel<<<1, 32>>>();
    pack_kernel<<<512, thr>>>(Wq, Wih, Whh, bih, bhh);

    // keys[b,e,a] = enc[b,e,:] . W_key[a,:] ; then transpose to [b][a][e]
    gemm_abt_kernel<<<dim3((B_*TE_)/64, A_/64), thr>>>(enc, Wk, keys_p, A_, H_, nullptr);
    transpose_kernel<<<dim3(TE_/32, A_/32, B_), dim3(32, 8)>>>();

    persist_kernel<<<GRID_, thr>>>(x, enc, v);

    // out[b,t,:] = h_hist[b,t,:] @ Wfc^T + bfc
    gemm_abt_kernel<<<dim3((B_*T_)/64, OUT_/64), thr>>>(hist_p, Wfc, (float*)d_out, OUT_, H_, bfc);
}

// round 11
// speedup vs baseline: 1.2432x; 1.0763x over previous
#include <cuda_runtime.h>
#include <math.h>

#define B_    64
#define T_    128
#define IN_   64
#define TE_   256
#define H_    512
#define A_    256
#define OUT_  64
#define G4_   2048
#define KIN_  1088
#define GRID_ 128

__device__ float g_keys [B_*TE_*A_];
__device__ float g_keysT[B_*A_*TE_];
__device__ float g_WqT [H_*A_];            // [k][a]
__device__ float g_Wp  [G4_*KIN_];
__device__ float g_bias[G4_];
__device__ float g_inp [B_*KIN_];
__device__ float g_h   [B_*H_];
__device__ float g_qp  [2*B_*A_];          // q partials: [hf][b][a]
__device__ float g_part[4*B_*G4_];
__device__ float g_hist[B_*T_*H_];
__device__ unsigned g_bar;                 // root epoch counter
__device__ unsigned g_barg[8];             // group counters

__device__ __forceinline__ float sigf(float xx) {
    return 1.0f / (1.0f + __expf(-xx));
}
__device__ __forceinline__ float tanha(float xx) {
    float y;
    asm("tanh.approx.f32 %0, %1;" : "=f"(y) : "f"(xx));
    return y;
}

// hierarchical grid barrier: 16-way group atomics + 8-way root; nanosleep poll
__device__ __forceinline__ void gbar(unsigned& nb) {
    nb += 1;
    __syncthreads();
    if (threadIdx.x == 0) {
        __threadfence();
        unsigned ret = atomicAdd(&g_barg[blockIdx.x & 7], 1u);
        if (ret == nb * 16u - 1u)
            atomicAdd(&g_bar, 1u);
        volatile unsigned* p = &g_bar;
        while (*p < nb * 8u) __nanosleep(32);
        __threadfence();
    }
    __syncthreads();
}

__device__ __forceinline__ float blk_reduce_max(float vv, float* red) {
#pragma unroll
    for (int o = 16; o > 0; o >>= 1)
        vv = fmaxf(vv, __shfl_xor_sync(0xffffffffu, vv, o));
    if ((threadIdx.x & 31) == 0) red[threadIdx.x >> 5] = vv;
    __syncthreads();
    if (threadIdx.x == 0) {
        float mm = red[0];
#pragma unroll
        for (int i = 1; i < 8; i++) mm = fmaxf(mm, red[i]);
        red[0] = mm;
    }
    __syncthreads();
    float r = red[0];
    __syncthreads();
    return r;
}
__device__ __forceinline__ float blk_reduce_sum(float vv, float* red) {
#pragma unroll
    for (int o = 16; o > 0; o >>= 1)
        vv += __shfl_xor_sync(0xffffffffu, vv, o);
    if ((threadIdx.x & 31) == 0) red[threadIdx.x >> 5] = vv;
    __syncthreads();
    if (threadIdx.x == 0) {
        float ss = red[0];
#pragma unroll
        for (int i = 1; i < 8; i++) ss += red[i];
        red[0] = ss;
    }
    __syncthreads();
    float r = red[0];
    __syncthreads();
    return r;
}

// 64x64xK tile GEMM: C = A(64,K) * B(64,K)^T, smem double-buffered, 4x4/thread.
template<bool CG>
__device__ __forceinline__ void tile_gemm64(
    const float* __restrict__ Ag, int lda,
    const float* __restrict__ Bg, int ldb,
    int nc, float* S, float acc[4][4])
{
    float (*As)[16][68] = (float(*)[16][68])S;
    float (*Bs)[16][68] = (float(*)[16][68])(S + 2176);
    const int tid = threadIdx.x;
    const int lrow = tid >> 2, lk = (tid & 3) << 2;
    const int tm = (tid & 15) << 2, tn = (tid >> 4) << 2;
    Ag += (size_t)lrow * lda + lk;
    Bg += (size_t)lrow * ldb + lk;
#pragma unroll
    for (int i = 0; i < 4; i++)
#pragma unroll
        for (int j = 0; j < 4; j++) acc[i][j] = 0.f;

    float4 ra = CG ? __ldcg((const float4*)Ag) : *(const float4*)Ag;
    float4 rb = *(const float4*)Bg;
    int buf = 0;
    As[0][lk + 0][lrow] = ra.x; As[0][lk + 1][lrow] = ra.y;
    As[0][lk + 2][lrow] = ra.z; As[0][lk + 3][lrow] = ra.w;
    Bs[0][lk + 0][lrow] = rb.x; Bs[0][lk + 1][lrow] = rb.y;
    Bs[0][lk + 2][lrow] = rb.z; Bs[0][lk + 3][lrow] = rb.w;
    __syncthreads();

    for (int c = 0; c < nc; c++) {
        if (c + 1 < nc) {
            const float4* ap = (const float4*)(Ag + (c + 1) * 16);
            ra = CG ? __ldcg(ap) : *ap;
            rb = *(const float4*)(Bg + (c + 1) * 16);
        }
#pragma unroll
        for (int kk = 0; kk < 16; kk++) {
            float4 av = *(const float4*)&As[buf][kk][tm];
            float4 bv = *(const float4*)&Bs[buf][kk][tn];
            acc[0][0] += av.x * bv.x; acc[0][1] += av.x * bv.y;
            acc[0][2] += av.x * bv.z; acc[0][3] += av.x * bv.w;
            acc[1][0] += av.y * bv.x; acc[1][1] += av.y * bv.y;
            acc[1][2] += av.y * bv.z; acc[1][3] += av.y * bv.w;
            acc[2][0] += av.z * bv.x; acc[2][1] += av.z * bv.y;
            acc[2][2] += av.z * bv.z; acc[2][3] += av.z * bv.w;
            acc[3][0] += av.w * bv.x; acc[3][1] += av.w * bv.y;
            acc[3][2] += av.w * bv.z; acc[3][3] += av.w * bv.w;
        }
        __syncthreads();
        if (c + 1 < nc) {
            buf ^= 1;
            As[buf][lk + 0][lrow] = ra.x; As[buf][lk + 1][lrow] = ra.y;
            As[buf][lk + 2][lrow] = ra.z; As[buf][lk + 3][lrow] = ra.w;
            Bs[buf][lk + 0][lrow] = rb.x; Bs[buf][lk + 1][lrow] = rb.y;
            Bs[buf][lk + 2][lrow] = rb.z; Bs[buf][lk + 3][lrow] = rb.w;
            __syncthreads();
        }
    }
}

// ---------------- prologue / epilogue kernels ----------------
__global__ void reset_kernel() {
    if (blockIdx.x == 0 && threadIdx.x < 9) {
        if (threadIdx.x == 0) g_bar = 0u;
        else g_barg[threadIdx.x - 1] = 0u;
    }
}

__global__ void __launch_bounds__(256) pack_kernel(
    const float* __restrict__ Wq, const float* __restrict__ Wih,
    const float* __restrict__ Whh, const float* __restrict__ bih,
    const float* __restrict__ bhh)
{
    int i = blockIdx.x * 256 + threadIdx.x;
    int s = gridDim.x * 256;
    for (int j = i; j < G4_ * KIN_; j += s) {
        int n = j / KIN_, k = j % KIN_;
        g_Wp[j] = (k < 576) ? Wih[(size_t)n * 576 + k]
                            : Whh[(size_t)n * H_ + (k - 576)];
    }
    for (int j = i; j < G4_; j += s) g_bias[j] = bih[j] + bhh[j];
    for (int j = i; j < H_ * A_; j += s) {
        int k = j / A_, a = j % A_;
        g_WqT[j] = Wq[(size_t)a * H_ + k];
    }
}

__global__ void transpose_kernel() {
    __shared__ float tile[32][33];
    int b = blockIdx.z;
    int e0 = blockIdx.x * 32, a0 = blockIdx.y * 32;
    const float* src = g_keys + ((size_t)b * TE_ + e0) * A_ + a0;
    for (int r = threadIdx.y; r < 32; r += 8)
        tile[r][threadIdx.x] = src[(size_t)r * A_ + threadIdx.x];
    __syncthreads();
    float* dst = g_keysT + ((size_t)b * A_ + a0) * TE_ + e0;
    for (int r = threadIdx.y; r < 32; r += 8)
        dst[(size_t)r * TE_ + threadIdx.x] = tile[threadIdx.x][r];
}

__global__ void __launch_bounds__(256) gemm_abt_kernel(
    const float* __restrict__ Am, const float* __restrict__ Bm,
    float* __restrict__ Cm, int N, int K, const float* __restrict__ bias)
{
    __shared__ float S[4352];
    float acc[4][4];
    const int m0 = blockIdx.x * 64, n0 = blockIdx.y * 64;
    tile_gemm64<false>(Am + (size_t)m0 * K, K, Bm + (size_t)n0 * K, K, K >> 4, S, acc);
    const int tid = threadIdx.x;
    const int tm = (tid & 15) << 2, tn = (tid >> 4) << 2;
    float b0 = 0.f, b1 = 0.f, b2 = 0.f, b3 = 0.f;
    if (bias) {
        b0 = bias[n0 + tn + 0]; b1 = bias[n0 + tn + 1];
        b2 = bias[n0 + tn + 2]; b3 = bias[n0 + tn + 3];
    }
#pragma unroll
    for (int i = 0; i < 4; i++) {
        float4 o;
        o.x = acc[i][0] + b0; o.y = acc[i][1] + b1;
        o.z = acc[i][2] + b2; o.w = acc[i][3] + b3;
        *(float4*)&Cm[(size_t)(m0 + tm + i) * N + n0 + tn] = o;
    }
}

// ---------------- persistent decoder: 3 barriers/step ----------------
__global__ void __launch_bounds__(256, 1) persist_kernel(
    const float* __restrict__ x, const float* __restrict__ enc,
    const float* __restrict__ v)
{
    __shared__ float S[4352];
    __shared__ float sq[A_], sv[A_], sw[TE_], sred[8];
    __shared__ float h_loc[256];
    __shared__ float4 sctx[256];
    const int tid = threadIdx.x, bid = blockIdx.x;
    unsigned ep = 0;
    const int b0 = bid >> 1, hf = bid & 1;
    const int u0 = hf * 256 + tid;
    float c_reg = 0.f;

    // init: h(-1)=0, q-partials(t=0)=0
    if (bid < 64) {
        for (int u = tid; u < H_; u += 256) {
            g_h[(size_t)bid * H_ + u] = 0.f;
            g_inp[(size_t)bid * KIN_ + 576 + u] = 0.f;
        }
    }
    sv[tid] = v[tid];
    g_qp[bid * 256 + tid] = 0.f;      // 128*256 = 2*B*A exactly
    gbar(ep);

    for (int t = 0; t < T_; t++) {
        // ==== P2: attention on ALL 128 CTAs; pair (b, dh) shares a batch ====
        {
            const int b = b0, dh = hf;
            sq[tid] = __ldcg(&g_qp[b * A_ + tid])
                    + __ldcg(&g_qp[B_ * A_ + b * A_ + tid]);
            __syncthreads();
            // energies (duplicated across the pair; deterministic identical)
            float e = 0.f;
            const float* kp = g_keysT + ((size_t)b * A_) * TE_ + tid;
#pragma unroll 8
            for (int a = 0; a < A_; a++)
                e += sv[a] * tanha(sq[a] + kp[(size_t)a * TE_]);
            float mx = blk_reduce_max(e, sred);
            float wv = __expf(e - mx);
            float sm = blk_reduce_sum(wv, sred);
            sw[tid] = wv * __fdividef(1.f, sm);
            if (dh == 0 && tid < IN_)
                g_inp[b * KIN_ + tid] = x[((size_t)b * T_ + t) * IN_ + tid];
            __syncthreads();
            // context: this CTA covers d-floats [dh*256, dh*256+256) = 64 float4
            const int d4 = tid & 63, th = tid >> 6;          // 4-way e-split
            float4 acc = {0.f, 0.f, 0.f, 0.f};
            const float4* ebase =
                (const float4*)(enc + (size_t)b * TE_ * H_ + dh * 256) + d4;
#pragma unroll 4
            for (int e2 = th * 64; e2 < th * 64 + 64; e2++) {
                float ww = sw[e2];
                float4 ev = ebase[(size_t)e2 * (H_ / 4)];
                acc.x += ww * ev.x; acc.y += ww * ev.y;
                acc.z += ww * ev.z; acc.w += ww * ev.w;
            }
            sctx[tid] = acc;
            __syncthreads();
            if (tid < 64) {
                float4 a0 = sctx[tid],       a1 = sctx[64 + tid];
                float4 a2 = sctx[128 + tid], a3 = sctx[192 + tid];
                float4 o;
                o.x = (a0.x + a1.x) + (a2.x + a3.x);
                o.y = (a0.y + a1.y) + (a2.y + a3.y);
                o.z = (a0.z + a1.z) + (a2.z + a3.z);
                o.w = (a0.w + a1.w) + (a2.w + a3.w);
                *(float4*)&g_inp[b * KIN_ + IN_ + dh * 256 + tid * 4] = o;
            }
        }
        gbar(ep);

        // ======== P5: gates GEMM partials (all 128 CTAs) ========
        {
            const int nt = bid >> 2, ks = bid & 3;
            float acc[4][4];
            tile_gemm64<true>(g_inp + ks * 272, KIN_,
                              g_Wp + (size_t)(nt * 64) * KIN_ + ks * 272, KIN_, 17, S, acc);
            const int tm = (tid & 15) << 2, tn = (tid >> 4) << 2;
            float* C = g_part + (size_t)ks * (B_ * G4_);
#pragma unroll
            for (int i = 0; i < 4; i++) {
                float4 o = {acc[i][0], acc[i][1], acc[i][2], acc[i][3]};
                *(float4*)&C[(size_t)(tm + i) * G4_ + nt * 64 + tn] = o;
            }
        }
        gbar(ep);

        // ======== P0: combine + LSTM cell + q-partial for next step ========
        {
            float gi = g_bias[u0], gf = g_bias[H_ + u0];
            float gg = g_bias[2 * H_ + u0], go = g_bias[3 * H_ + u0];
#pragma unroll
            for (int p = 0; p < 4; p++) {
                const float* pp = g_part + (size_t)p * (B_ * G4_) + b0 * G4_;
                gi += __ldcg(&pp[u0]);
                gf += __ldcg(&pp[H_ + u0]);
                gg += __ldcg(&pp[2 * H_ + u0]);
                go += __ldcg(&pp[3 * H_ + u0]);
            }
            float cn = sigf(gf) * c_reg + sigf(gi) * tanhf(gg);
            float hn = sigf(go) * tanhf(cn);
            c_reg = cn;
            g_h[(size_t)b0 * H_ + u0] = hn;
            g_inp[(size_t)b0 * KIN_ + 576 + u0] = hn;
            g_hist[((size_t)b0 * T_ + t) * H_ + u0] = hn;
            h_loc[tid] = hn;
        }
        __syncthreads();
        // q-partial for step t+1: a = tid; sum over this CTA's 256 h-units.
        {
            float qa = 0.f;
            const float* wt = g_WqT + (size_t)(hf * 256) * A_ + tid;
#pragma unroll 8
            for (int j = 0; j < 256; j++)
                qa += h_loc[j] * wt[(size_t)j * A_];
            g_qp[(size_t)hf * (B_ * A_) + b0 * A_ + tid] = qa;
        }
        gbar(ep);
    }
}

// ---------------------------------------------------------------------------
extern "C" void kernel_launch(void* const* d_in, const int* in_sizes, int n_in,
                              void* d_out, int out_size)
{
    const float* x   = (const float*)d_in[0];
    const float* enc = (const float*)d_in[1];
    const float* Wq  = (const float*)d_in[2];
    const float* Wk  = (const float*)d_in[3];
    const float* v   = (const float*)d_in[4];
    const float* Wih = (const float*)d_in[5];
    const float* Whh = (const float*)d_in[6];
    const float* bih = (const float*)d_in[7];
    const float* bhh = (const float*)d_in[8];
    const float* Wfc = (const float*)d_in[9];
    const float* bfc = (const float*)d_in[10];

    float* keys_p = nullptr;
    float* hist_p = nullptr;
    cudaGetSymbolAddress((void**)&keys_p, g_keys);
    cudaGetSymbolAddress((void**)&hist_p, g_hist);

    dim3 thr(256);

    reset_kernel<<<1, 32>>>();
    pack_kernel<<<512, thr>>>(Wq, Wih, Whh, bih, bhh);

    // keys[b,e,a] = enc[b,e,:] . W_key[a,:] ; then transpose to [b][a][e]
    gemm_abt_kernel<<<dim3((B_*TE_)/64, A_/64), thr>>>(enc, Wk, keys_p, A_, H_, nullptr);
    transpose_kernel<<<dim3(TE_/32, A_/32, B_), dim3(32, 8)>>>();

    persist_kernel<<<GRID_, thr>>>(x, enc, v);

    // out[b,t,:] = h_hist[b,t,:] @ Wfc^T + bfc
    gemm_abt_kernel<<<dim3((B_*T_)/64, OUT_/64), thr>>>(hist_p, Wfc, (float*)d_out, OUT_, H_, bfc);
}

// round 12
// speedup vs baseline: 1.2470x; 1.0031x over previous
#include <cuda_runtime.h>
#include <math.h>

#define B_    64
#define T_    128
#define IN_   64
#define TE_   256
#define H_    512
#define A_    256
#define OUT_  64
#define G4_   2048
#define KIN_  1088
#define GRID_ 128

__device__ float g_keys [B_*TE_*A_];
__device__ float g_keysT[B_*A_*TE_];
__device__ float g_WqT [H_*A_];            // [k][a]
__device__ float g_Wp  [G4_*KIN_];
__device__ float g_bias[G4_];
__device__ float g_inp [B_*KIN_];
__device__ float g_h   [B_*H_];
__device__ float g_qp  [2*B_*A_];          // q partials: [hf][b][a]
__device__ float g_part[4*B_*G4_];
__device__ float g_hist[B_*T_*H_];
__device__ unsigned g_bar;                 // root epoch counter
__device__ unsigned g_barg[8];             // group counters

__device__ __forceinline__ float sigf(float xx) {
    return 1.0f / (1.0f + __expf(-xx));
}
__device__ __forceinline__ float tanha(float xx) {
    float y;
    asm("tanh.approx.f32 %0, %1;" : "=f"(y) : "f"(xx));
    return y;
}

// ---- packed f32x2 helpers (FFMA2: 2 IEEE fp32 MACs per instruction) ----
__device__ __forceinline__ void ffma2(unsigned long long& d,
                                      unsigned long long a,
                                      unsigned long long b) {
    asm("fma.rn.f32x2 %0, %1, %2, %0;" : "+l"(d) : "l"(a), "l"(b));
}
__device__ __forceinline__ unsigned long long bcast2(float x) {
    unsigned long long r;
    unsigned u = __float_as_uint(x);
    asm("mov.b64 %0, {%1, %1};" : "=l"(r) : "r"(u));
    return r;
}
__device__ __forceinline__ void unpack2(unsigned long long p, float& lo, float& hi) {
    unsigned a, b;
    asm("mov.b64 {%0, %1}, %2;" : "=r"(a), "=r"(b) : "l"(p));
    lo = __uint_as_float(a);
    hi = __uint_as_float(b);
}

// hierarchical grid barrier: 16-way group atomics + 8-way root; nanosleep poll
__device__ __forceinline__ void gbar(unsigned& nb) {
    nb += 1;
    __syncthreads();
    if (threadIdx.x == 0) {
        __threadfence();
        unsigned ret = atomicAdd(&g_barg[blockIdx.x & 7], 1u);
        if (ret == nb * 16u - 1u)
            atomicAdd(&g_bar, 1u);
        volatile unsigned* p = &g_bar;
        while (*p < nb * 8u) __nanosleep(32);
        __threadfence();
    }
    __syncthreads();
}

__device__ __forceinline__ float blk_reduce_max(float vv, float* red) {
#pragma unroll
    for (int o = 16; o > 0; o >>= 1)
        vv = fmaxf(vv, __shfl_xor_sync(0xffffffffu, vv, o));
    if ((threadIdx.x & 31) == 0) red[threadIdx.x >> 5] = vv;
    __syncthreads();
    if (threadIdx.x == 0) {
        float mm = red[0];
#pragma unroll
        for (int i = 1; i < 8; i++) mm = fmaxf(mm, red[i]);
        red[0] = mm;
    }
    __syncthreads();
    float r = red[0];
    __syncthreads();
    return r;
}
__device__ __forceinline__ float blk_reduce_sum(float vv, float* red) {
#pragma unroll
    for (int o = 16; o > 0; o >>= 1)
        vv += __shfl_xor_sync(0xffffffffu, vv, o);
    if ((threadIdx.x & 31) == 0) red[threadIdx.x >> 5] = vv;
    __syncthreads();
    if (threadIdx.x == 0) {
        float ss = red[0];
#pragma unroll
        for (int i = 1; i < 8; i++) ss += red[i];
        red[0] = ss;
    }
    __syncthreads();
    float r = red[0];
    __syncthreads();
    return r;
}

// 64x64xK tile GEMM: C = A(64,K) * B(64,K)^T, smem double-buffered.
// Inner loop uses packed fma.rn.f32x2 (2 MACs per fma-pipe issue).
template<bool CG>
__device__ __forceinline__ void tile_gemm64(
    const float* __restrict__ Ag, int lda,
    const float* __restrict__ Bg, int ldb,
    int nc, float* S, float acc[4][4])
{
    float (*As)[16][68] = (float(*)[16][68])S;
    float (*Bs)[16][68] = (float(*)[16][68])(S + 2176);
    const int tid = threadIdx.x;
    const int lrow = tid >> 2, lk = (tid & 3) << 2;
    const int tm = (tid & 15) << 2, tn = (tid >> 4) << 2;
    Ag += (size_t)lrow * lda + lk;
    Bg += (size_t)lrow * ldb + lk;

    unsigned long long accp[4][2];
    const unsigned long long z2 = bcast2(0.f);
#pragma unroll
    for (int i = 0; i < 4; i++) { accp[i][0] = z2; accp[i][1] = z2; }

    float4 ra = CG ? __ldcg((const float4*)Ag) : *(const float4*)Ag;
    float4 rb = *(const float4*)Bg;
    int buf = 0;
    As[0][lk + 0][lrow] = ra.x; As[0][lk + 1][lrow] = ra.y;
    As[0][lk + 2][lrow] = ra.z; As[0][lk + 3][lrow] = ra.w;
    Bs[0][lk + 0][lrow] = rb.x; Bs[0][lk + 1][lrow] = rb.y;
    Bs[0][lk + 2][lrow] = rb.z; Bs[0][lk + 3][lrow] = rb.w;
    __syncthreads();

    for (int c = 0; c < nc; c++) {
        if (c + 1 < nc) {
            const float4* ap = (const float4*)(Ag + (c + 1) * 16);
            ra = CG ? __ldcg(ap) : *ap;
            rb = *(const float4*)(Bg + (c + 1) * 16);
        }
#pragma unroll
        for (int kk = 0; kk < 16; kk++) {
            float4 av = *(const float4*)&As[buf][kk][tm];
            ulonglong2 bv = *(const ulonglong2*)&Bs[buf][kk][tn];
            unsigned long long a0 = bcast2(av.x), a1 = bcast2(av.y);
            unsigned long long a2 = bcast2(av.z), a3 = bcast2(av.w);
            ffma2(accp[0][0], a0, bv.x); ffma2(accp[0][1], a0, bv.y);
            ffma2(accp[1][0], a1, bv.x); ffma2(accp[1][1], a1, bv.y);
            ffma2(accp[2][0], a2, bv.x); ffma2(accp[2][1], a2, bv.y);
            ffma2(accp[3][0], a3, bv.x); ffma2(accp[3][1], a3, bv.y);
        }
        __syncthreads();
        if (c + 1 < nc) {
            buf ^= 1;
            As[buf][lk + 0][lrow] = ra.x; As[buf][lk + 1][lrow] = ra.y;
            As[buf][lk + 2][lrow] = ra.z; As[buf][lk + 3][lrow] = ra.w;
            Bs[buf][lk + 0][lrow] = rb.x; Bs[buf][lk + 1][lrow] = rb.y;
            Bs[buf][lk + 2][lrow] = rb.z; Bs[buf][lk + 3][lrow] = rb.w;
            __syncthreads();
        }
    }

#pragma unroll
    for (int i = 0; i < 4; i++) {
        unpack2(accp[i][0], acc[i][0], acc[i][1]);
        unpack2(accp[i][1], acc[i][2], acc[i][3]);
    }
}

// ---------------- prologue / epilogue kernels ----------------
__global__ void reset_kernel() {
    if (blockIdx.x == 0 && threadIdx.x < 9) {
        if (threadIdx.x == 0) g_bar = 0u;
        else g_barg[threadIdx.x - 1] = 0u;
    }
}

__global__ void __launch_bounds__(256) pack_kernel(
    const float* __restrict__ Wq, const float* __restrict__ Wih,
    const float* __restrict__ Whh, const float* __restrict__ bih,
    const float* __restrict__ bhh)
{
    int i = blockIdx.x * 256 + threadIdx.x;
    int s = gridDim.x * 256;
    for (int j = i; j < G4_ * KIN_; j += s) {
        int n = j / KIN_, k = j % KIN_;
        g_Wp[j] = (k < 576) ? Wih[(size_t)n * 576 + k]
                            : Whh[(size_t)n * H_ + (k - 576)];
    }
    for (int j = i; j < G4_; j += s) g_bias[j] = bih[j] + bhh[j];
    for (int j = i; j < H_ * A_; j += s) {
        int k = j / A_, a = j % A_;
        g_WqT[j] = Wq[(size_t)a * H_ + k];
    }
}

__global__ void transpose_kernel() {
    __shared__ float tile[32][33];
    int b = blockIdx.z;
    int e0 = blockIdx.x * 32, a0 = blockIdx.y * 32;
    const float* src = g_keys + ((size_t)b * TE_ + e0) * A_ + a0;
    for (int r = threadIdx.y; r < 32; r += 8)
        tile[r][threadIdx.x] = src[(size_t)r * A_ + threadIdx.x];
    __syncthreads();
    float* dst = g_keysT + ((size_t)b * A_ + a0) * TE_ + e0;
    for (int r = threadIdx.y; r < 32; r += 8)
        dst[(size_t)r * TE_ + threadIdx.x] = tile[threadIdx.x][r];
}

__global__ void __launch_bounds__(256) gemm_abt_kernel(
    const float* __restrict__ Am, const float* __restrict__ Bm,
    float* __restrict__ Cm, int N, int K, const float* __restrict__ bias)
{
    __shared__ float S[4352];
    float acc[4][4];
    const int m0 = blockIdx.x * 64, n0 = blockIdx.y * 64;
    tile_gemm64<false>(Am + (size_t)m0 * K, K, Bm + (size_t)n0 * K, K, K >> 4, S, acc);
    const int tid = threadIdx.x;
    const int tm = (tid & 15) << 2, tn = (tid >> 4) << 2;
    float b0 = 0.f, b1 = 0.f, b2 = 0.f, b3 = 0.f;
    if (bias) {
        b0 = bias[n0 + tn + 0]; b1 = bias[n0 + tn + 1];
        b2 = bias[n0 + tn + 2]; b3 = bias[n0 + tn + 3];
    }
#pragma unroll
    for (int i = 0; i < 4; i++) {
        float4 o;
        o.x = acc[i][0] + b0; o.y = acc[i][1] + b1;
        o.z = acc[i][2] + b2; o.w = acc[i][3] + b3;
        *(float4*)&Cm[(size_t)(m0 + tm + i) * N + n0 + tn] = o;
    }
}

// ---------------- persistent decoder: 3 barriers/step ----------------
__global__ void __launch_bounds__(256, 1) persist_kernel(
    const float* __restrict__ x, const float* __restrict__ enc,
    const float* __restrict__ v)
{
    __shared__ float S[4352];
    __shared__ float sq[A_], sv[A_], sw[TE_], sred[8];
    __shared__ float h_loc[256];
    __shared__ float4 sctx[256];
    const int tid = threadIdx.x, bid = blockIdx.x;
    unsigned ep = 0;
    const int b0 = bid >> 1, hf = bid & 1;
    const int u0 = hf * 256 + tid;
    float c_reg = 0.f;

    // init: h(-1)=0, q-partials(t=0)=0
    if (bid < 64) {
        for (int u = tid; u < H_; u += 256) {
            g_h[(size_t)bid * H_ + u] = 0.f;
            g_inp[(size_t)bid * KIN_ + 576 + u] = 0.f;
        }
    }
    sv[tid] = v[tid];
    g_qp[bid * 256 + tid] = 0.f;      // 128*256 = 2*B*A exactly
    gbar(ep);

    for (int t = 0; t < T_; t++) {
        // ==== P2: attention on ALL 128 CTAs; pair (b, dh) shares a batch ====
        {
            const int b = b0, dh = hf;
            sq[tid] = __ldcg(&g_qp[b * A_ + tid])
                    + __ldcg(&g_qp[B_ * A_ + b * A_ + tid]);
            __syncthreads();
            // energies (duplicated across the pair; deterministic identical)
            float e = 0.f;
            const float* kp = g_keysT + ((size_t)b * A_) * TE_ + tid;
#pragma unroll 8
            for (int a = 0; a < A_; a++)
                e += sv[a] * tanha(sq[a] + kp[(size_t)a * TE_]);
            float mx = blk_reduce_max(e, sred);
            float wv = __expf(e - mx);
            float sm = blk_reduce_sum(wv, sred);
            sw[tid] = wv * __fdividef(1.f, sm);
            if (dh == 0 && tid < IN_)
                g_inp[b * KIN_ + tid] = x[((size_t)b * T_ + t) * IN_ + tid];
            __syncthreads();
            // context: this CTA covers d-floats [dh*256, dh*256+256) = 64 float4
            const int d4 = tid & 63, th = tid >> 6;          // 4-way e-split
            float4 acc = {0.f, 0.f, 0.f, 0.f};
            const float4* ebase =
                (const float4*)(enc + (size_t)b * TE_ * H_ + dh * 256) + d4;
#pragma unroll 4
            for (int e2 = th * 64; e2 < th * 64 + 64; e2++) {
                float ww = sw[e2];
                float4 ev = ebase[(size_t)e2 * (H_ / 4)];
                acc.x += ww * ev.x; acc.y += ww * ev.y;
                acc.z += ww * ev.z; acc.w += ww * ev.w;
            }
            sctx[tid] = acc;
            __syncthreads();
            if (tid < 64) {
                float4 a0 = sctx[tid],       a1 = sctx[64 + tid];
                float4 a2 = sctx[128 + tid], a3 = sctx[192 + tid];
                float4 o;
                o.x = (a0.x + a1.x) + (a2.x + a3.x);
                o.y = (a0.y + a1.y) + (a2.y + a3.y);
                o.z = (a0.z + a1.z) + (a2.z + a3.z);
                o.w = (a0.w + a1.w) + (a2.w + a3.w);
                *(float4*)&g_inp[b * KIN_ + IN_ + dh * 256 + tid * 4] = o;
            }
        }
        gbar(ep);

        // ======== P5: gates GEMM partials (all 128 CTAs) ========
        {
            const int nt = bid >> 2, ks = bid & 3;
            float acc[4][4];
            tile_gemm64<true>(g_inp + ks * 272, KIN_,
                              g_Wp + (size_t)(nt * 64) * KIN_ + ks * 272, KIN_, 17, S, acc);
            const int tm = (tid & 15) << 2, tn = (tid >> 4) << 2;
            float* C = g_part + (size_t)ks * (B_ * G4_);
#pragma unroll
            for (int i = 0; i < 4; i++) {
                float4 o = {acc[i][0], acc[i][1], acc[i][2], acc[i][3]};
                *(float4*)&C[(size_t)(tm + i) * G4_ + nt * 64 + tn] = o;
            }
        }
        gbar(ep);

        // ======== P0: combine + LSTM cell + q-partial for next step ========
        {
            float gi = g_bias[u0], gf = g_bias[H_ + u0];
            float gg = g_bias[2 * H_ + u0], go = g_bias[3 * H_ + u0];
#pragma unroll
            for (int p = 0; p < 4; p++) {
                const float* pp = g_part + (size_t)p * (B_ * G4_) + b0 * G4_;
                gi += __ldcg(&pp[u0]);
                gf += __ldcg(&pp[H_ + u0]);
                gg += __ldcg(&pp[2 * H_ + u0]);
                go += __ldcg(&pp[3 * H_ + u0]);
            }
            float cn = sigf(gf) * c_reg + sigf(gi) * tanhf(gg);
            float hn = sigf(go) * tanhf(cn);
            c_reg = cn;
            g_h[(size_t)b0 * H_ + u0] = hn;
            g_inp[(size_t)b0 * KIN_ + 576 + u0] = hn;
            g_hist[((size_t)b0 * T_ + t) * H_ + u0] = hn;
            h_loc[tid] = hn;
        }
        __syncthreads();
        // q-partial for step t+1: a = tid; sum over this CTA's 256 h-units.
        {
            float qa = 0.f;
            const float* wt = g_WqT + (size_t)(hf * 256) * A_ + tid;
#pragma unroll 8
            for (int j = 0; j < 256; j++)
                qa += h_loc[j] * wt[(size_t)j * A_];
            g_qp[(size_t)hf * (B_ * A_) + b0 * A_ + tid] = qa;
        }
        gbar(ep);
    }
}

// ---------------------------------------------------------------------------
extern "C" void kernel_launch(void* const* d_in, const int* in_sizes, int n_in,
                              void* d_out, int out_size)
{
    const float* x   = (const float*)d_in[0];
    const float* enc = (const float*)d_in[1];
    const float* Wq  = (const float*)d_in[2];
    const float* Wk  = (const float*)d_in[3];
    const float* v   = (const float*)d_in[4];
    const float* Wih = (const float*)d_in[5];
    const float* Whh = (const float*)d_in[6];
    const float* bih = (const float*)d_in[7];
    const float* bhh = (const float*)d_in[8];
    const float* Wfc = (const float*)d_in[9];
    const float* bfc = (const float*)d_in[10];

    float* keys_p = nullptr;
    float* hist_p = nullptr;
    cudaGetSymbolAddress((void**)&keys_p, g_keys);
    cudaGetSymbolAddress((void**)&hist_p, g_hist);

    dim3 thr(256);

    reset_kernel<<<1, 32>>>();
    pack_kernel<<<512, thr>>>(Wq, Wih, Whh, bih, bhh);

    // keys[b,e,a] = enc[b,e,:] . W_key[a,:] ; then transpose to [b][a][e]
    gemm_abt_kernel<<<dim3((B_*TE_)/64, A_/64), thr>>>(enc, Wk, keys_p, A_, H_, nullptr);
    transpose_kernel<<<dim3(TE_/32, A_/32, B_), dim3(32, 8)>>>();

    persist_kernel<<<GRID_, thr>>>(x, enc, v);

    // out[b,t,:] = h_hist[b,t,:] @ Wfc^T + bfc
    gemm_abt_kernel<<<dim3((B_*T_)/64, OUT_/64), thr>>>(hist_p, Wfc, (float*)d_out, OUT_, H_, bfc);
}

// round 13
// speedup vs baseline: 1.2852x; 1.0306x over previous
#include <cuda_runtime.h>
#include <cuda_fp16.h>
#include <math.h>

#define B_    64
#define T_    128
#define IN_   64
#define TE_   256
#define H_    512
#define A_    256
#define OUT_  64
#define G4_   2048
#define KIN_  1088
#define GRID_ 128

__device__ float  g_keys [B_*TE_*A_];
__device__ __half g_keysTh[B_*A_*TE_];     // fp16 transposed keys [b][a][t']
__device__ __half g_encH [B_*TE_*H_];      // fp16 encoder copy (P2 ctx only)
__device__ float  g_WqT [H_*A_];           // [k][a]
__device__ float  g_Wp  [G4_*KIN_];
__device__ float  g_bias[G4_];
__device__ float  g_inp [B_*KIN_];
__device__ float  g_h   [B_*H_];
__device__ float  g_qp  [2*B_*A_];         // q partials: [hf][b][a]
__device__ float  g_part[4*B_*G4_];
__device__ float  g_hist[B_*T_*H_];
__device__ unsigned g_bar;                 // root epoch counter
__device__ unsigned g_barg[8];             // group counters

__device__ __forceinline__ float sigf(float xx) {
    return 1.0f / (1.0f + __expf(-xx));
}
__device__ __forceinline__ float tanha(float xx) {
    float y;
    asm("tanh.approx.f32 %0, %1;" : "=f"(y) : "f"(xx));
    return y;
}

// ---- packed f32x2 helpers (FFMA2: 2 IEEE fp32 MACs per instruction) ----
__device__ __forceinline__ void ffma2(unsigned long long& d,
                                      unsigned long long a,
                                      unsigned long long b) {
    asm("fma.rn.f32x2 %0, %1, %2, %0;" : "+l"(d) : "l"(a), "l"(b));
}
__device__ __forceinline__ unsigned long long bcast2(float x) {
    unsigned long long r;
    unsigned u = __float_as_uint(x);
    asm("mov.b64 %0, {%1, %1};" : "=l"(r) : "r"(u));
    return r;
}
__device__ __forceinline__ void unpack2(unsigned long long p, float& lo, float& hi) {
    unsigned a, b;
    asm("mov.b64 {%0, %1}, %2;" : "=r"(a), "=r"(b) : "l"(p));
    lo = __uint_as_float(a);
    hi = __uint_as_float(b);
}

// hierarchical grid barrier; release fence only (all mutable reads are .cg)
__device__ __forceinline__ void gbar(unsigned& nb) {
    nb += 1;
    __syncthreads();
    if (threadIdx.x == 0) {
        __threadfence();                       // release: order prior stores
        unsigned ret = atomicAdd(&g_barg[blockIdx.x & 7], 1u);
        if (ret == nb * 16u - 1u)
            atomicAdd(&g_bar, 1u);
        volatile unsigned* p = &g_bar;
        while (*p < nb * 8u) __nanosleep(32);
        // no acquire fence: subsequent .cg loads issue in order after the poll
    }
    __syncthreads();
}

__device__ __forceinline__ float blk_reduce_max(float vv, float* red) {
#pragma unroll
    for (int o = 16; o > 0; o >>= 1)
        vv = fmaxf(vv, __shfl_xor_sync(0xffffffffu, vv, o));
    if ((threadIdx.x & 31) == 0) red[threadIdx.x >> 5] = vv;
    __syncthreads();
    if (threadIdx.x == 0) {
        float mm = red[0];
#pragma unroll
        for (int i = 1; i < 8; i++) mm = fmaxf(mm, red[i]);
        red[0] = mm;
    }
    __syncthreads();
    float r = red[0];
    __syncthreads();
    return r;
}
__device__ __forceinline__ float blk_reduce_sum(float vv, float* red) {
#pragma unroll
    for (int o = 16; o > 0; o >>= 1)
        vv += __shfl_xor_sync(0xffffffffu, vv, o);
    if ((threadIdx.x & 31) == 0) red[threadIdx.x >> 5] = vv;
    __syncthreads();
    if (threadIdx.x == 0) {
        float ss = red[0];
#pragma unroll
        for (int i = 1; i < 8; i++) ss += red[i];
        red[0] = ss;
    }
    __syncthreads();
    float r = red[0];
    __syncthreads();
    return r;
}

// 64x64xK tile GEMM with packed fma.rn.f32x2 inner loop (proven R12)
template<bool CG>
__device__ __forceinline__ void tile_gemm64(
    const float* __restrict__ Ag, int lda,
    const float* __restrict__ Bg, int ldb,
    int nc, float* S, float acc[4][4])
{
    float (*As)[16][68] = (float(*)[16][68])S;
    float (*Bs)[16][68] = (float(*)[16][68])(S + 2176);
    const int tid = threadIdx.x;
    const int lrow = tid >> 2, lk = (tid & 3) << 2;
    const int tm = (tid & 15) << 2, tn = (tid >> 4) << 2;
    Ag += (size_t)lrow * lda + lk;
    Bg += (size_t)lrow * ldb + lk;

    unsigned long long accp[4][2];
    const unsigned long long z2 = bcast2(0.f);
#pragma unroll
    for (int i = 0; i < 4; i++) { accp[i][0] = z2; accp[i][1] = z2; }

    float4 ra = CG ? __ldcg((const float4*)Ag) : *(const float4*)Ag;
    float4 rb = *(const float4*)Bg;
    int buf = 0;
    As[0][lk + 0][lrow] = ra.x; As[0][lk + 1][lrow] = ra.y;
    As[0][lk + 2][lrow] = ra.z; As[0][lk + 3][lrow] = ra.w;
    Bs[0][lk + 0][lrow] = rb.x; Bs[0][lk + 1][lrow] = rb.y;
    Bs[0][lk + 2][lrow] = rb.z; Bs[0][lk + 3][lrow] = rb.w;
    __syncthreads();

    for (int c = 0; c < nc; c++) {
        if (c + 1 < nc) {
            const float4* ap = (const float4*)(Ag + (c + 1) * 16);
            ra = CG ? __ldcg(ap) : *ap;
            rb = *(const float4*)(Bg + (c + 1) * 16);
        }
#pragma unroll
        for (int kk = 0; kk < 16; kk++) {
            float4 av = *(const float4*)&As[buf][kk][tm];
            ulonglong2 bv = *(const ulonglong2*)&Bs[buf][kk][tn];
            unsigned long long a0 = bcast2(av.x), a1 = bcast2(av.y);
            unsigned long long a2 = bcast2(av.z), a3 = bcast2(av.w);
            ffma2(accp[0][0], a0, bv.x); ffma2(accp[0][1], a0, bv.y);
            ffma2(accp[1][0], a1, bv.x); ffma2(accp[1][1], a1, bv.y);
            ffma2(accp[2][0], a2, bv.x); ffma2(accp[2][1], a2, bv.y);
            ffma2(accp[3][0], a3, bv.x); ffma2(accp[3][1], a3, bv.y);
        }
        __syncthreads();
        if (c + 1 < nc) {
            buf ^= 1;
            As[buf][lk + 0][lrow] = ra.x; As[buf][lk + 1][lrow] = ra.y;
            As[buf][lk + 2][lrow] = ra.z; As[buf][lk + 3][lrow] = ra.w;
            Bs[buf][lk + 0][lrow] = rb.x; Bs[buf][lk + 1][lrow] = rb.y;
            Bs[buf][lk + 2][lrow] = rb.z; Bs[buf][lk + 3][lrow] = rb.w;
            __syncthreads();
        }
    }

#pragma unroll
    for (int i = 0; i < 4; i++) {
        unpack2(accp[i][0], acc[i][0], acc[i][1]);
        unpack2(accp[i][1], acc[i][2], acc[i][3]);
    }
}

// ---------------- prologue / epilogue kernels ----------------
__global__ void reset_kernel() {
    if (blockIdx.x == 0 && threadIdx.x < 9) {
        if (threadIdx.x == 0) g_bar = 0u;
        else g_barg[threadIdx.x - 1] = 0u;
    }
}

__global__ void __launch_bounds__(256) pack_kernel(
    const float* __restrict__ Wq, const float* __restrict__ Wih,
    const float* __restrict__ Whh, const float* __restrict__ bih,
    const float* __restrict__ bhh, const float* __restrict__ enc)
{
    int i = blockIdx.x * 256 + threadIdx.x;
    int s = gridDim.x * 256;
    for (int j = i; j < G4_ * KIN_; j += s) {
        int n = j / KIN_, k = j % KIN_;
        g_Wp[j] = (k < 576) ? Wih[(size_t)n * 576 + k]
                            : Whh[(size_t)n * H_ + (k - 576)];
    }
    for (int j = i; j < G4_; j += s) g_bias[j] = bih[j] + bhh[j];
    for (int j = i; j < H_ * A_; j += s) {
        int k = j / A_, a = j % A_;
        g_WqT[j] = Wq[(size_t)a * H_ + k];
    }
    for (int j = i; j < B_ * TE_ * H_; j += s)
        g_encH[j] = __float2half(enc[j]);
}

__global__ void transpose_kernel() {
    __shared__ float tile[32][33];
    int b = blockIdx.z;
    int e0 = blockIdx.x * 32, a0 = blockIdx.y * 32;
    const float* src = g_keys + ((size_t)b * TE_ + e0) * A_ + a0;
    for (int r = threadIdx.y; r < 32; r += 8)
        tile[r][threadIdx.x] = src[(size_t)r * A_ + threadIdx.x];
    __syncthreads();
    __half* dst = g_keysTh + ((size_t)b * A_ + a0) * TE_ + e0;
    for (int r = threadIdx.y; r < 32; r += 8)
        dst[(size_t)r * TE_ + threadIdx.x] = __float2half(tile[threadIdx.x][r]);
}

__global__ void __launch_bounds__(256) gemm_abt_kernel(
    const float* __restrict__ Am, const float* __restrict__ Bm,
    float* __restrict__ Cm, int N, int K, const float* __restrict__ bias)
{
    __shared__ float S[4352];
    float acc[4][4];
    const int m0 = blockIdx.x * 64, n0 = blockIdx.y * 64;
    tile_gemm64<false>(Am + (size_t)m0 * K, K, Bm + (size_t)n0 * K, K, K >> 4, S, acc);
    const int tid = threadIdx.x;
    const int tm = (tid & 15) << 2, tn = (tid >> 4) << 2;
    float b0 = 0.f, b1 = 0.f, b2 = 0.f, b3 = 0.f;
    if (bias) {
        b0 = bias[n0 + tn + 0]; b1 = bias[n0 + tn + 1];
        b2 = bias[n0 + tn + 2]; b3 = bias[n0 + tn + 3];
    }
#pragma unroll
    for (int i = 0; i < 4; i++) {
        float4 o;
        o.x = acc[i][0] + b0; o.y = acc[i][1] + b1;
        o.z = acc[i][2] + b2; o.w = acc[i][3] + b3;
        *(float4*)&Cm[(size_t)(m0 + tm + i) * N + n0 + tn] = o;
    }
}

// ---------------- persistent decoder: 3 barriers/step ----------------
__global__ void __launch_bounds__(256, 1) persist_kernel(
    const float* __restrict__ x, const float* __restrict__ enc,
    const float* __restrict__ v)
{
    __shared__ float S[4352];
    __shared__ float sq[A_], sv[A_], sw[TE_], sred[8];
    __shared__ float h_loc[256];
    __shared__ float4 sctx[256];
    const int tid = threadIdx.x, bid = blockIdx.x;
    unsigned ep = 0;
    const int b0 = bid >> 1, hf = bid & 1;
    const int u0 = hf * 256 + tid;
    float c_reg = 0.f;

    // init: h(-1)=0, q-partials(t=0)=0
    if (bid < 64) {
        for (int u = tid; u < H_; u += 256) {
            g_h[(size_t)bid * H_ + u] = 0.f;
            g_inp[(size_t)bid * KIN_ + 576 + u] = 0.f;
        }
    }
    sv[tid] = v[tid];
    g_qp[bid * 256 + tid] = 0.f;      // 128*256 = 2*B*A exactly
    gbar(ep);

    for (int t = 0; t < T_; t++) {
        // ==== P2: attention on ALL 128 CTAs; pair (b, dh) shares a batch ====
        {
            const int b = b0, dh = hf;
            sq[tid] = __ldcg(&g_qp[b * A_ + tid])
                    + __ldcg(&g_qp[B_ * A_ + b * A_ + tid]);
            __syncthreads();
            // energies (duplicated across the pair; deterministic identical)
            float e = 0.f;
            const __half* kp = g_keysTh + ((size_t)b * A_) * TE_ + tid;
#pragma unroll 8
            for (int a = 0; a < A_; a++)
                e += sv[a] * tanha(sq[a] + __half2float(kp[(size_t)a * TE_]));
            float mx = blk_reduce_max(e, sred);
            float wv = __expf(e - mx);
            float sm = blk_reduce_sum(wv, sred);
            sw[tid] = wv * __fdividef(1.f, sm);
            if (dh == 0 && tid < IN_)
                g_inp[b * KIN_ + tid] = x[((size_t)b * T_ + t) * IN_ + tid];
            __syncthreads();
            // context from fp16 enc copy: thread covers 4 d, 4-way e-split
            const int d4 = tid & 63, th = tid >> 6;
            float4 acc = {0.f, 0.f, 0.f, 0.f};
            const uint2* ebase =
                (const uint2*)(g_encH + (size_t)b * TE_ * H_ + dh * 256) + d4;
#pragma unroll 4
            for (int e2 = th * 64; e2 < th * 64 + 64; e2++) {
                float ww = sw[e2];
                uint2 ev = ebase[(size_t)e2 * (H_ / 4)];
                float2 f01 = __half22float2(*(const __half2*)&ev.x);
                float2 f23 = __half22float2(*(const __half2*)&ev.y);
                acc.x += ww * f01.x; acc.y += ww * f01.y;
                acc.z += ww * f23.x; acc.w += ww * f23.y;
            }
            sctx[tid] = acc;
            __syncthreads();
            if (tid < 64) {
                float4 a0 = sctx[tid],       a1 = sctx[64 + tid];
                float4 a2 = sctx[128 + tid], a3 = sctx[192 + tid];
                float4 o;
                o.x = (a0.x + a1.x) + (a2.x + a3.x);
                o.y = (a0.y + a1.y) + (a2.y + a3.y);
                o.z = (a0.z + a1.z) + (a2.z + a3.z);
                o.w = (a0.w + a1.w) + (a2.w + a3.w);
                *(float4*)&g_inp[b * KIN_ + IN_ + dh * 256 + tid * 4] = o;
            }
        }
        gbar(ep);

        // ======== P5: gates GEMM partials (all 128 CTAs) ========
        {
            const int nt = bid >> 2, ks = bid & 3;
            float acc[4][4];
            tile_gemm64<true>(g_inp + ks * 272, KIN_,
                              g_Wp + (size_t)(nt * 64) * KIN_ + ks * 272, KIN_, 17, S, acc);
            const int tm = (tid & 15) << 2, tn = (tid >> 4) << 2;
            float* C = g_part + (size_t)ks * (B_ * G4_);
#pragma unroll
            for (int i = 0; i < 4; i++) {
                float4 o = {acc[i][0], acc[i][1], acc[i][2], acc[i][3]};
                *(float4*)&C[(size_t)(tm + i) * G4_ + nt * 64 + tn] = o;
            }
        }
        gbar(ep);

        // ======== P0: combine + LSTM cell + q-partial for next step ========
        {
            float gi = g_bias[u0], gf = g_bias[H_ + u0];
            float gg = g_bias[2 * H_ + u0], go = g_bias[3 * H_ + u0];
#pragma unroll
            for (int p = 0; p < 4; p++) {
                const float* pp = g_part + (size_t)p * (B_ * G4_) + b0 * G4_;
                gi += __ldcg(&pp[u0]);
                gf += __ldcg(&pp[H_ + u0]);
                gg += __ldcg(&pp[2 * H_ + u0]);
                go += __ldcg(&pp[3 * H_ + u0]);
            }
            float cn = sigf(gf) * c_reg + sigf(gi) * tanhf(gg);
            float hn = sigf(go) * tanhf(cn);
            c_reg = cn;
            g_h[(size_t)b0 * H_ + u0] = hn;
            g_inp[(size_t)b0 * KIN_ + 576 + u0] = hn;
            g_hist[((size_t)b0 * T_ + t) * H_ + u0] = hn;
            h_loc[tid] = hn;
        }
        __syncthreads();
        // q-partial for step t+1: a = tid; sum over this CTA's 256 h-units.
        {
            float qa = 0.f;
            const float* wt = g_WqT + (size_t)(hf * 256) * A_ + tid;
#pragma unroll 8
            for (int j = 0; j < 256; j++)
                qa += h_loc[j] * wt[(size_t)j * A_];
            g_qp[(size_t)hf * (B_ * A_) + b0 * A_ + tid] = qa;
        }
        gbar(ep);
    }
}

// ---------------------------------------------------------------------------
extern "C" void kernel_launch(void* const* d_in, const int* in_sizes, int n_in,
                              void* d_out, int out_size)
{
    const float* x   = (const float*)d_in[0];
    const float* enc = (const float*)d_in[1];
    const float* Wq  = (const float*)d_in[2];
    const float* Wk  = (const float*)d_in[3];
    const float* v   = (const float*)d_in[4];
    const float* Wih = (const float*)d_in[5];
    const float* Whh = (const float*)d_in[6];
    const float* bih = (const float*)d_in[7];
    const float* bhh = (const float*)d_in[8];
    const float* Wfc = (const float*)d_in[9];
    const float* bfc = (const float*)d_in[10];

    float* keys_p = nullptr;
    float* hist_p = nullptr;
    cudaGetSymbolAddress((void**)&keys_p, g_keys);
    cudaGetSymbolAddress((void**)&hist_p, g_hist);

    dim3 thr(256);

    reset_kernel<<<1, 32>>>();
    pack_kernel<<<512, thr>>>(Wq, Wih, Whh, bih, bhh, enc);

    // keys[b,e,a] = enc[b,e,:] . W_key[a,:] ; transpose -> fp16 [b][a][e]
    gemm_abt_kernel<<<dim3((B_*TE_)/64, A_/64), thr>>>(enc, Wk, keys_p, A_, H_, nullptr);
    transpose_kernel<<<dim3(TE_/32, A_/32, B_), dim3(32, 8)>>>();

    persist_kernel<<<GRID_, thr>>>(x, enc, v);

    // out[b,t,:] = h_hist[b,t,:] @ Wfc^T + bfc
    gemm_abt_kernel<<<dim3((B_*T_)/64, OUT_/64), thr>>>(hist_p, Wfc, (float*)d_out, OUT_, H_, bfc);
}

// round 15
// speedup vs baseline: 1.3015x; 1.0127x over previous
#include <cuda_runtime.h>
#include <cuda_fp16.h>
#include <math.h>

#define B_    64
#define T_    128
#define IN_   64
#define TE_   256
#define H_    512
#define A_    256
#define OUT_  64
#define G4_   2048
#define KIN_  1088
#define GRID_ 128

__device__ float  g_keys [B_*TE_*A_];
__device__ __half g_keysTh[B_*A_*TE_];     // fp16 transposed keys [b][a][t']
__device__ __half g_encH [B_*TE_*H_];      // fp16 encoder copy (P2 ctx only)
__device__ float  g_WqT [H_*A_];           // [k][a]
__device__ float  g_Wp  [G4_*KIN_];
__device__ float  g_bias[G4_];
__device__ float  g_inp [B_*KIN_];
__device__ float  g_h   [B_*H_];
__device__ float  g_qp  [2*B_*A_];         // q partials: [hf][b][a]
__device__ float  g_part[4*B_*G4_];
__device__ float  g_hist[B_*T_*H_];
__device__ unsigned g_bar;                 // root epoch counter
__device__ unsigned g_barg[8];             // group counters
__device__ unsigned g_qflag[GRID_];        // pair-exchange epoch flags

__device__ __forceinline__ float sigf(float xx) {
    return 1.0f / (1.0f + __expf(-xx));
}
__device__ __forceinline__ float tanha(float xx) {
    float y;
    asm("tanh.approx.f32 %0, %1;" : "=f"(y) : "f"(xx));
    return y;
}

// ---- packed f32x2 helpers ----
__device__ __forceinline__ void ffma2(unsigned long long& d,
                                      unsigned long long a,
                                      unsigned long long b) {
    asm("fma.rn.f32x2 %0, %1, %2, %0;" : "+l"(d) : "l"(a), "l"(b));
}
__device__ __forceinline__ unsigned long long bcast2(float x) {
    unsigned long long r;
    unsigned u = __float_as_uint(x);
    asm("mov.b64 %0, {%1, %1};" : "=l"(r) : "r"(u));
    return r;
}
__device__ __forceinline__ void unpack2(unsigned long long p, float& lo, float& hi) {
    unsigned a, b;
    asm("mov.b64 {%0, %1}, %2;" : "=r"(a), "=r"(b) : "l"(p));
    lo = __uint_as_float(a);
    hi = __uint_as_float(b);
}
__device__ __forceinline__ unsigned ldcg_u(const unsigned* p) {
    unsigned v;
    asm volatile("ld.global.cg.u32 %0, [%1];" : "=r"(v) : "l"(p) : "memory");
    return v;
}

// hierarchical grid barrier; release fence only (all mutable reads are .cg)
__device__ __forceinline__ void gbar(unsigned& nb) {
    nb += 1;
    __syncthreads();
    if (threadIdx.x == 0) {
        __threadfence();
        unsigned ret = atomicAdd(&g_barg[blockIdx.x & 7], 1u);
        if (ret == nb * 16u - 1u)
            atomicAdd(&g_bar, 1u);
        volatile unsigned* p = &g_bar;
        while (*p < nb * 8u) __nanosleep(32);
    }
    __syncthreads();
}

__device__ __forceinline__ float blk_reduce_max(float vv, float* red) {
#pragma unroll
    for (int o = 16; o > 0; o >>= 1)
        vv = fmaxf(vv, __shfl_xor_sync(0xffffffffu, vv, o));
    if ((threadIdx.x & 31) == 0) red[threadIdx.x >> 5] = vv;
    __syncthreads();
    if (threadIdx.x == 0) {
        float mm = red[0];
#pragma unroll
        for (int i = 1; i < 8; i++) mm = fmaxf(mm, red[i]);
        red[0] = mm;
    }
    __syncthreads();
    float r = red[0];
    __syncthreads();
    return r;
}
__device__ __forceinline__ float blk_reduce_sum(float vv, float* red) {
#pragma unroll
    for (int o = 16; o > 0; o >>= 1)
        vv += __shfl_xor_sync(0xffffffffu, vv, o);
    if ((threadIdx.x & 31) == 0) red[threadIdx.x >> 5] = vv;
    __syncthreads();
    if (threadIdx.x == 0) {
        float ss = red[0];
#pragma unroll
        for (int i = 1; i < 8; i++) ss += red[i];
        red[0] = ss;
    }
    __syncthreads();
    float r = red[0];
    __syncthreads();
    return r;
}

// 64x64xK tile GEMM with packed fma.rn.f32x2 inner loop (proven)
template<bool CG>
__device__ __forceinline__ void tile_gemm64(
    const float* __restrict__ Ag, int lda,
    const float* __restrict__ Bg, int ldb,
    int nc, float* S, float acc[4][4])
{
    float (*As)[16][68] = (float(*)[16][68])S;
    float (*Bs)[16][68] = (float(*)[16][68])(S + 2176);
    const int tid = threadIdx.x;
    const int lrow = tid >> 2, lk = (tid & 3) << 2;
    const int tm = (tid & 15) << 2, tn = (tid >> 4) << 2;
    Ag += (size_t)lrow * lda + lk;
    Bg += (size_t)lrow * ldb + lk;

    unsigned long long accp[4][2];
    const unsigned long long z2 = bcast2(0.f);
#pragma unroll
    for (int i = 0; i < 4; i++) { accp[i][0] = z2; accp[i][1] = z2; }

    float4 ra = CG ? __ldcg((const float4*)Ag) : *(const float4*)Ag;
    float4 rb = *(const float4*)Bg;
    int buf = 0;
    As[0][lk + 0][lrow] = ra.x; As[0][lk + 1][lrow] = ra.y;
    As[0][lk + 2][lrow] = ra.z; As[0][lk + 3][lrow] = ra.w;
    Bs[0][lk + 0][lrow] = rb.x; Bs[0][lk + 1][lrow] = rb.y;
    Bs[0][lk + 2][lrow] = rb.z; Bs[0][lk + 3][lrow] = rb.w;
    __syncthreads();

    for (int c = 0; c < nc; c++) {
        if (c + 1 < nc) {
            const float4* ap = (const float4*)(Ag + (c + 1) * 16);
            ra = CG ? __ldcg(ap) : *ap;
            rb = *(const float4*)(Bg + (c + 1) * 16);
        }
#pragma unroll
        for (int kk = 0; kk < 16; kk++) {
            float4 av = *(const float4*)&As[buf][kk][tm];
            ulonglong2 bv = *(const ulonglong2*)&Bs[buf][kk][tn];
            unsigned long long a0 = bcast2(av.x), a1 = bcast2(av.y);
            unsigned long long a2 = bcast2(av.z), a3 = bcast2(av.w);
            ffma2(accp[0][0], a0, bv.x); ffma2(accp[0][1], a0, bv.y);
            ffma2(accp[1][0], a1, bv.x); ffma2(accp[1][1], a1, bv.y);
            ffma2(accp[2][0], a2, bv.x); ffma2(accp[2][1], a2, bv.y);
            ffma2(accp[3][0], a3, bv.x); ffma2(accp[3][1], a3, bv.y);
        }
        __syncthreads();
        if (c + 1 < nc) {
            buf ^= 1;
            As[buf][lk + 0][lrow] = ra.x; As[buf][lk + 1][lrow] = ra.y;
            As[buf][lk + 2][lrow] = ra.z; As[buf][lk + 3][lrow] = ra.w;
            Bs[buf][lk + 0][lrow] = rb.x; Bs[buf][lk + 1][lrow] = rb.y;
            Bs[buf][lk + 2][lrow] = rb.z; Bs[buf][lk + 3][lrow] = rb.w;
            __syncthreads();
        }
    }

#pragma unroll
    for (int i = 0; i < 4; i++) {
        unpack2(accp[i][0], acc[i][0], acc[i][1]);
        unpack2(accp[i][1], acc[i][2], acc[i][3]);
    }
}

// ---------------- prologue / epilogue kernels ----------------
__global__ void reset_kernel() {
    int tid = threadIdx.x;
    if (tid == 0) g_bar = 0u;
    if (tid >= 1 && tid < 9) g_barg[tid - 1] = 0u;
    if (tid < GRID_) g_qflag[tid] = 0u;
}

__global__ void __launch_bounds__(256) pack_kernel(
    const float* __restrict__ Wq, const float* __restrict__ Wih,
    const float* __restrict__ Whh, const float* __restrict__ bih,
    const float* __restrict__ bhh, const float* __restrict__ enc)
{
    int i = blockIdx.x * 256 + threadIdx.x;
    int s = gridDim.x * 256;
    for (int j = i; j < G4_ * KIN_; j += s) {
        int n = j / KIN_, k = j % KIN_;
        g_Wp[j] = (k < 576) ? Wih[(size_t)n * 576 + k]
                            : Whh[(size_t)n * H_ + (k - 576)];
    }
    for (int j = i; j < G4_; j += s) g_bias[j] = bih[j] + bhh[j];
    for (int j = i; j < H_ * A_; j += s) {
        int k = j / A_, a = j % A_;
        g_WqT[j] = Wq[(size_t)a * H_ + k];
    }
    for (int j = i; j < B_ * TE_ * H_; j += s)
        g_encH[j] = __float2half(enc[j]);
}

__global__ void transpose_kernel() {
    __shared__ float tile[32][33];
    int b = blockIdx.z;
    int e0 = blockIdx.x * 32, a0 = blockIdx.y * 32;
    const float* src = g_keys + ((size_t)b * TE_ + e0) * A_ + a0;
    for (int r = threadIdx.y; r < 32; r += 8)
        tile[r][threadIdx.x] = src[(size_t)r * A_ + threadIdx.x];
    __syncthreads();
    __half* dst = g_keysTh + ((size_t)b * A_ + a0) * TE_ + e0;
    for (int r = threadIdx.y; r < 32; r += 8)
        dst[(size_t)r * TE_ + threadIdx.x] = __float2half(tile[threadIdx.x][r]);
}

__global__ void __launch_bounds__(256) gemm_abt_kernel(
    const float* __restrict__ Am, const float* __restrict__ Bm,
    float* __restrict__ Cm, int N, int K, const float* __restrict__ bias)
{
    __shared__ float S[4352];
    float acc[4][4];
    const int m0 = blockIdx.x * 64, n0 = blockIdx.y * 64;
    tile_gemm64<false>(Am + (size_t)m0 * K, K, Bm + (size_t)n0 * K, K, K >> 4, S, acc);
    const int tid = threadIdx.x;
    const int tm = (tid & 15) << 2, tn = (tid >> 4) << 2;
    float b0 = 0.f, b1 = 0.f, b2 = 0.f, b3 = 0.f;
    if (bias) {
        b0 = bias[n0 + tn + 0]; b1 = bias[n0 + tn + 1];
        b2 = bias[n0 + tn + 2]; b3 = bias[n0 + tn + 3];
    }
#pragma unroll
    for (int i = 0; i < 4; i++) {
        float4 o;
        o.x = acc[i][0] + b0; o.y = acc[i][1] + b1;
        o.z = acc[i][2] + b2; o.w = acc[i][3] + b3;
        *(float4*)&Cm[(size_t)(m0 + tm + i) * N + n0 + tn] = o;
    }
}

// ---------------- persistent decoder: 2 grid barriers/step ----------------
__global__ void __launch_bounds__(256, 1) persist_kernel(
    const float* __restrict__ x, const float* __restrict__ enc,
    const float* __restrict__ v)
{
    __shared__ float S[4352];
    __shared__ float sq[A_], sv[A_], sw[TE_], sred[8];
    __shared__ float h_loc[256];
    __shared__ float4 sctx[256];
    const int tid = threadIdx.x, bid = blockIdx.x;
    const int partner = bid ^ 1;
    unsigned ep = 0;
    const int b0 = bid >> 1, hf = bid & 1;
    const int u0 = hf * 256 + tid;
    float c_reg = 0.f;

    // init: h(-1)=0, q-partials(t=0)=0
    if (bid < 64) {
        for (int u = tid; u < H_; u += 256) {
            g_h[(size_t)bid * H_ + u] = 0.f;
            g_inp[(size_t)bid * KIN_ + 576 + u] = 0.f;
        }
    }
    sv[tid] = v[tid];
    g_qp[bid * 256 + tid] = 0.f;      // 128*256 = 2*B*A exactly
    gbar(ep);

    for (int t = 0; t < T_; t++) {
        // ==== Phase A: cell(t-1) + q-tail + pair-sync + attention(t) ====
        if (t > 0) {
            // cell for step t-1 (consumes partials from last phase B)
            float gi = g_bias[u0], gf = g_bias[H_ + u0];
            float gg = g_bias[2 * H_ + u0], go = g_bias[3 * H_ + u0];
#pragma unroll
            for (int p = 0; p < 4; p++) {
                const float* pp = g_part + (size_t)p * (B_ * G4_) + b0 * G4_;
                gi += __ldcg(&pp[u0]);
                gf += __ldcg(&pp[H_ + u0]);
                gg += __ldcg(&pp[2 * H_ + u0]);
                go += __ldcg(&pp[3 * H_ + u0]);
            }
            float cn = sigf(gf) * c_reg + sigf(gi) * tanhf(gg);
            float hn = sigf(go) * tanhf(cn);
            c_reg = cn;
            g_h[(size_t)b0 * H_ + u0] = hn;
            g_inp[(size_t)b0 * KIN_ + 576 + u0] = hn;
            g_hist[((size_t)b0 * T_ + (t - 1)) * H_ + u0] = hn;
            h_loc[tid] = hn;
            __syncthreads();
            // q-partial for this half: a = tid, sum over CTA's 256 h-units
            {
                float qa = 0.f;
                const float* wt = g_WqT + (size_t)(hf * 256) * A_ + tid;
#pragma unroll 8
                for (int j = 0; j < 256; j++)
                    qa += h_loc[j] * wt[(size_t)j * A_];
                g_qp[(size_t)hf * (B_ * A_) + b0 * A_ + tid] = qa;
            }
            __syncthreads();
            // pair exchange: publish then wait for partner's epoch
            if (tid == 0) {
                __threadfence();
                atomicExch(&g_qflag[bid], (unsigned)t);
                while (ldcg_u(&g_qflag[partner]) < (unsigned)t) __nanosleep(20);
            }
            __syncthreads();
        }
        // attention for step t (both pair CTAs: identical softmax, split ctx)
        {
            const int b = b0, dh = hf;
            sq[tid] = __ldcg(&g_qp[b * A_ + tid])
                    + __ldcg(&g_qp[B_ * A_ + b * A_ + tid]);
            __syncthreads();
            float e = 0.f;
            const __half* kp = g_keysTh + ((size_t)b * A_) * TE_ + tid;
#pragma unroll 8
            for (int a = 0; a < A_; a++)
                e += sv[a] * tanha(sq[a] + __half2float(kp[(size_t)a * TE_]));
            float mx = blk_reduce_max(e, sred);
            float wv = __expf(e - mx);
            float sm = blk_reduce_sum(wv, sred);
            sw[tid] = wv * __fdividef(1.f, sm);
            if (dh == 0 && tid < IN_)
                g_inp[b * KIN_ + tid] = x[((size_t)b * T_ + t) * IN_ + tid];
            __syncthreads();
            const int d4 = tid & 63, th = tid >> 6;
            float4 acc = {0.f, 0.f, 0.f, 0.f};
            const uint2* ebase =
                (const uint2*)(g_encH + (size_t)b * TE_ * H_ + dh * 256) + d4;
#pragma unroll 4
            for (int e2 = th * 64; e2 < th * 64 + 64; e2++) {
                float ww = sw[e2];
                uint2 ev = ebase[(size_t)e2 * (H_ / 4)];
                float2 f01 = __half22float2(*(const __half2*)&ev.x);
                float2 f23 = __half22float2(*(const __half2*)&ev.y);
                acc.x += ww * f01.x; acc.y += ww * f01.y;
                acc.z += ww * f23.x; acc.w += ww * f23.y;
            }
            sctx[tid] = acc;
            __syncthreads();
            if (tid < 64) {
                float4 a0 = sctx[tid],       a1 = sctx[64 + tid];
                float4 a2 = sctx[128 + tid], a3 = sctx[192 + tid];
                float4 o;
                o.x = (a0.x + a1.x) + (a2.x + a3.x);
                o.y = (a0.y + a1.y) + (a2.y + a3.y);
                o.z = (a0.z + a1.z) + (a2.z + a3.z);
                o.w = (a0.w + a1.w) + (a2.w + a3.w);
                *(float4*)&g_inp[b * KIN_ + IN_ + dh * 256 + tid * 4] = o;
            }
        }
        gbar(ep);

        // ==== Phase B: gates GEMM partials (all 128 CTAs) ====
        {
            const int nt = bid >> 2, ks = bid & 3;
            float acc[4][4];
            tile_gemm64<true>(g_inp + ks * 272, KIN_,
                              g_Wp + (size_t)(nt * 64) * KIN_ + ks * 272, KIN_, 17, S, acc);
            const int tm = (tid & 15) << 2, tn = (tid >> 4) << 2;
            float* C = g_part + (size_t)ks * (B_ * G4_);
#pragma unroll
            for (int i = 0; i < 4; i++) {
                float4 o = {acc[i][0], acc[i][1], acc[i][2], acc[i][3]};
                *(float4*)&C[(size_t)(tm + i) * G4_ + nt * 64 + tn] = o;
            }
        }
        gbar(ep);
    }

    // final cell for step T-1 (h_hist[127]); no attention follows
    {
        float gi = g_bias[u0], gf = g_bias[H_ + u0];
        float gg = g_bias[2 * H_ + u0], go = g_bias[3 * H_ + u0];
#pragma unroll
        for (int p = 0; p < 4; p++) {
            const float* pp = g_part + (size_t)p * (B_ * G4_) + b0 * G4_;
            gi += __ldcg(&pp[u0]);
            gf += __ldcg(&pp[H_ + u0]);
            gg += __ldcg(&pp[2 * H_ + u0]);
            go += __ldcg(&pp[3 * H_ + u0]);
        }
        float cn = sigf(gf) * c_reg + sigf(gi) * tanhf(gg);
        float hn = sigf(go) * tanhf(cn);
        g_hist[((size_t)b0 * T_ + (T_ - 1)) * H_ + u0] = hn;
    }
}

// ---------------------------------------------------------------------------
extern "C" void kernel_launch(void* const* d_in, const int* in_sizes, int n_in,
                              void* d_out, int out_size)
{
    const float* x   = (const float*)d_in[0];
    const float* enc = (const float*)d_in[1];
    const float* Wq  = (const float*)d_in[2];
    const float* Wk  = (const float*)d_in[3];
    const float* v   = (const float*)d_in[4];
    const float* Wih = (const float*)d_in[5];
    const float* Whh = (const float*)d_in[6];
    const float* bih = (const float*)d_in[7];
    const float* bhh = (const float*)d_in[8];
    const float* Wfc = (const float*)d_in[9];
    const float* bfc = (const float*)d_in[10];

    float* keys_p = nullptr;
    float* hist_p = nullptr;
    cudaGetSymbolAddress((void**)&keys_p, g_keys);
    cudaGetSymbolAddress((void**)&hist_p, g_hist);

    dim3 thr(256);

    reset_kernel<<<1, 256>>>();
    pack_kernel<<<512, thr>>>(Wq, Wih, Whh, bih, bhh, enc);

    // keys[b,e,a] = enc[b,e,:] . W_key[a,:] ; transpose -> fp16 [b][a][e]
    gemm_abt_kernel<<<dim3((B_*TE_)/64, A_/64), thr>>>(enc, Wk, keys_p, A_, H_, nullptr);
    transpose_kernel<<<dim3(TE_/32, A_/32, B_), dim3(32, 8)>>>();

    persist_kernel<<<GRID_, thr>>>(x, enc, v);

    // out[b,t,:] = h_hist[b,t,:] @ Wfc^T + bfc
    gemm_abt_kernel<<<dim3((B_*T_)/64, OUT_/64), thr>>>(hist_p, Wfc, (float*)d_out, OUT_, H_, bfc);
}

// round 17
// speedup vs baseline: 1.5027x; 1.1546x over previous
#include <cuda_runtime.h>
#include <cuda_fp16.h>
#include <math.h>

#define B_    64
#define T_    128
#define IN_   64
#define TE_   256
#define H_    512
#define A_    256
#define OUT_  64
#define G4_   2048
#define KIN_  1088
#define GRID_ 128
#define WQ_SMEM_BYTES (256 * 256 * 2)

__device__ float  g_keys [B_*TE_*A_];
__device__ __half g_keysTh[B_*A_*TE_];     // fp16 transposed keys [b][a][t']
__device__ __half g_encH [B_*TE_*H_];      // fp16 encoder copy (ctx only)
__device__ float  g_WqT [H_*A_];           // [k][a]
__device__ float  g_Wp  [G4_*KIN_];
__device__ float  g_bias[G4_];
__device__ float  g_inp [B_*KIN_];
__device__ float  g_h   [B_*H_];
__device__ float  g_qp  [2*B_*A_];         // q partials: [hf][b][a]
__device__ float  g_part[4*B_*G4_];
__device__ float  g_hist[B_*T_*H_];
__device__ unsigned g_bar;                 // root epoch counter
__device__ unsigned g_barg[8];             // group counters
__device__ unsigned g_qflag[GRID_];        // pair-exchange epoch flags

__device__ __forceinline__ float sigf(float xx) {
    return 1.0f / (1.0f + __expf(-xx));
}
__device__ __forceinline__ float tanha(float xx) {
    float y;
    asm("tanh.approx.f32 %0, %1;" : "=f"(y) : "f"(xx));
    return y;
}

// ---- packed f32x2 helpers ----
__device__ __forceinline__ void ffma2(unsigned long long& d,
                                      unsigned long long a,
                                      unsigned long long b) {
    asm("fma.rn.f32x2 %0, %1, %2, %0;" : "+l"(d) : "l"(a), "l"(b));
}
__device__ __forceinline__ unsigned long long bcast2(float x) {
    unsigned long long r;
    unsigned u = __float_as_uint(x);
    asm("mov.b64 %0, {%1, %1};" : "=l"(r) : "r"(u));
    return r;
}
__device__ __forceinline__ void unpack2(unsigned long long p, float& lo, float& hi) {
    unsigned a, b;
    asm("mov.b64 {%0, %1}, %2;" : "=r"(a), "=r"(b) : "l"(p));
    lo = __uint_as_float(a);
    hi = __uint_as_float(b);
}
__device__ __forceinline__ unsigned ldcg_u(const unsigned* p) {
    unsigned v;
    asm volatile("ld.global.cg.u32 %0, [%1];" : "=r"(v) : "l"(p) : "memory");
    return v;
}

// hierarchical grid barrier; release fence only (all mutable reads are .cg)
__device__ __forceinline__ void gbar(unsigned& nb) {
    nb += 1;
    __syncthreads();
    if (threadIdx.x == 0) {
        __threadfence();
        unsigned ret = atomicAdd(&g_barg[blockIdx.x & 7], 1u);
        if (ret == nb * 16u - 1u)
            atomicAdd(&g_bar, 1u);
        volatile unsigned* p = &g_bar;
        while (*p < nb * 8u) __nanosleep(32);
    }
    __syncthreads();
}

__device__ __forceinline__ float blk_reduce_max(float vv, float* red) {
#pragma unroll
    for (int o = 16; o > 0; o >>= 1)
        vv = fmaxf(vv, __shfl_xor_sync(0xffffffffu, vv, o));
    if ((threadIdx.x & 31) == 0) red[threadIdx.x >> 5] = vv;
    __syncthreads();
    if (threadIdx.x == 0) {
        float mm = red[0];
#pragma unroll
        for (int i = 1; i < 8; i++) mm = fmaxf(mm, red[i]);
        red[0] = mm;
    }
    __syncthreads();
    float r = red[0];
    __syncthreads();
    return r;
}
__device__ __forceinline__ float blk_reduce_sum(float vv, float* red) {
#pragma unroll
    for (int o = 16; o > 0; o >>= 1)
        vv += __shfl_xor_sync(0xffffffffu, vv, o);
    if ((threadIdx.x & 31) == 0) red[threadIdx.x >> 5] = vv;
    __syncthreads();
    if (threadIdx.x == 0) {
        float ss = red[0];
#pragma unroll
        for (int i = 1; i < 8; i++) ss += red[i];
        red[0] = ss;
    }
    __syncthreads();
    float r = red[0];
    __syncthreads();
    return r;
}

// 64x64xK tile GEMM with packed fma.rn.f32x2 inner loop (proven)
template<bool CG>
__device__ __forceinline__ void tile_gemm64(
    const float* __restrict__ Ag, int lda,
    const float* __restrict__ Bg, int ldb,
    int nc, float* S, float acc[4][4])
{
    float (*As)[16][68] = (float(*)[16][68])S;
    float (*Bs)[16][68] = (float(*)[16][68])(S + 2176);
    const int tid = threadIdx.x;
    const int lrow = tid >> 2, lk = (tid & 3) << 2;
    const int tm = (tid & 15) << 2, tn = (tid >> 4) << 2;
    Ag += (size_t)lrow * lda + lk;
    Bg += (size_t)lrow * ldb + lk;

    unsigned long long accp[4][2];
    const unsigned long long z2 = bcast2(0.f);
#pragma unroll
    for (int i = 0; i < 4; i++) { accp[i][0] = z2; accp[i][1] = z2; }

    float4 ra = CG ? __ldcg((const float4*)Ag) : *(const float4*)Ag;
    float4 rb = *(const float4*)Bg;
    int buf = 0;
    As[0][lk + 0][lrow] = ra.x; As[0][lk + 1][lrow] = ra.y;
    As[0][lk + 2][lrow] = ra.z; As[0][lk + 3][lrow] = ra.w;
    Bs[0][lk + 0][lrow] = rb.x; Bs[0][lk + 1][lrow] = rb.y;
    Bs[0][lk + 2][lrow] = rb.z; Bs[0][lk + 3][lrow] = rb.w;
    __syncthreads();

    for (int c = 0; c < nc; c++) {
        if (c + 1 < nc) {
            const float4* ap = (const float4*)(Ag + (c + 1) * 16);
            ra = CG ? __ldcg(ap) : *ap;
            rb = *(const float4*)(Bg + (c + 1) * 16);
        }
#pragma unroll
        for (int kk = 0; kk < 16; kk++) {
            float4 av = *(const float4*)&As[buf][kk][tm];
            ulonglong2 bv = *(const ulonglong2*)&Bs[buf][kk][tn];
            unsigned long long a0 = bcast2(av.x), a1 = bcast2(av.y);
            unsigned long long a2 = bcast2(av.z), a3 = bcast2(av.w);
            ffma2(accp[0][0], a0, bv.x); ffma2(accp[0][1], a0, bv.y);
            ffma2(accp[1][0], a1, bv.x); ffma2(accp[1][1], a1, bv.y);
            ffma2(accp[2][0], a2, bv.x); ffma2(accp[2][1], a2, bv.y);
            ffma2(accp[3][0], a3, bv.x); ffma2(accp[3][1], a3, bv.y);
        }
        __syncthreads();
        if (c + 1 < nc) {
            buf ^= 1;
            As[buf][lk + 0][lrow] = ra.x; As[buf][lk + 1][lrow] = ra.y;
            As[buf][lk + 2][lrow] = ra.z; As[buf][lk + 3][lrow] = ra.w;
            Bs[buf][lk + 0][lrow] = rb.x; Bs[buf][lk + 1][lrow] = rb.y;
            Bs[buf][lk + 2][lrow] = rb.z; Bs[buf][lk + 3][lrow] = rb.w;
            __syncthreads();
        }
    }

#pragma unroll
    for (int i = 0; i < 4; i++) {
        unpack2(accp[i][0], acc[i][0], acc[i][1]);
        unpack2(accp[i][1], acc[i][2], acc[i][3]);
    }
}

// ---------------- prologue / epilogue kernels ----------------
__global__ void reset_kernel() {
    int tid = threadIdx.x;
    if (tid == 0) g_bar = 0u;
    if (tid >= 1 && tid < 9) g_barg[tid - 1] = 0u;
    if (tid < GRID_) g_qflag[tid] = 0u;
}

__global__ void __launch_bounds__(256) pack_kernel(
    const float* __restrict__ Wq, const float* __restrict__ Wih,
    const float* __restrict__ Whh, const float* __restrict__ bih,
    const float* __restrict__ bhh, const float* __restrict__ enc)
{
    int i = blockIdx.x * 256 + threadIdx.x;
    int s = gridDim.x * 256;
    for (int j = i; j < G4_ * KIN_; j += s) {
        int n = j / KIN_, k = j % KIN_;
        g_Wp[j] = (k < 576) ? Wih[(size_t)n * 576 + k]
                            : Whh[(size_t)n * H_ + (k - 576)];
    }
    for (int j = i; j < G4_; j += s) g_bias[j] = bih[j] + bhh[j];
    for (int j = i; j < H_ * A_; j += s) {
        int k = j / A_, a = j % A_;
        g_WqT[j] = Wq[(size_t)a * H_ + k];
    }
    for (int j = i; j < B_ * TE_ * H_; j += s)
        g_encH[j] = __float2half(enc[j]);
}

__global__ void transpose_kernel() {
    __shared__ float tile[32][33];
    int b = blockIdx.z;
    int e0 = blockIdx.x * 32, a0 = blockIdx.y * 32;
    const float* src = g_keys + ((size_t)b * TE_ + e0) * A_ + a0;
    for (int r = threadIdx.y; r < 32; r += 8)
        tile[r][threadIdx.x] = src[(size_t)r * A_ + threadIdx.x];
    __syncthreads();
    __half* dst = g_keysTh + ((size_t)b * A_ + a0) * TE_ + e0;
    for (int r = threadIdx.y; r < 32; r += 8)
        dst[(size_t)r * TE_ + threadIdx.x] = __float2half(tile[threadIdx.x][r]);
}

__global__ void __launch_bounds__(256) gemm_abt_kernel(
    const float* __restrict__ Am, const float* __restrict__ Bm,
    float* __restrict__ Cm, int N, int K, const float* __restrict__ bias)
{
    __shared__ float S[4352];
    float acc[4][4];
    const int m0 = blockIdx.x * 64, n0 = blockIdx.y * 64;
    tile_gemm64<false>(Am + (size_t)m0 * K, K, Bm + (size_t)n0 * K, K, K >> 4, S, acc);
    const int tid = threadIdx.x;
    const int tm = (tid & 15) << 2, tn = (tid >> 4) << 2;
    float b0 = 0.f, b1 = 0.f, b2 = 0.f, b3 = 0.f;
    if (bias) {
        b0 = bias[n0 + tn + 0]; b1 = bias[n0 + tn + 1];
        b2 = bias[n0 + tn + 2]; b3 = bias[n0 + tn + 3];
    }
#pragma unroll
    for (int i = 0; i < 4; i++) {
        float4 o;
        o.x = acc[i][0] + b0; o.y = acc[i][1] + b1;
        o.z = acc[i][2] + b2; o.w = acc[i][3] + b3;
        *(float4*)&Cm[(size_t)(m0 + tm + i) * N + n0 + tn] = o;
    }
}

// ---------------- persistent decoder: 2 grid barriers/step ----------------
// Dynamic smem holds this CTA's half of WqT in fp16 (128 KB), loaded once.
__global__ void __launch_bounds__(256, 1) persist_kernel(
    const float* __restrict__ x, const float* __restrict__ enc,
    const float* __restrict__ v)
{
    extern __shared__ __half wq_s[];           // [256 k][256 a] fp16
    __shared__ float S[4352];
    __shared__ float sq[A_], sv[A_], sw[TE_], sred[8];
    __shared__ float h_loc[256];
    __shared__ float4 sctx[256];
    const int tid = threadIdx.x, bid = blockIdx.x;
    const int partner = bid ^ 1;
    unsigned ep = 0;
    const int b0 = bid >> 1, hf = bid & 1;
    const int u0 = hf * 256 + tid;
    float c_reg = 0.f;

    // one-time: cache WqT[hf*256 : hf*256+256][*] as fp16 in smem
    for (int j = 0; j < 256; j++)
        wq_s[j * 256 + tid] =
            __float2half(g_WqT[(size_t)(hf * 256 + j) * A_ + tid]);

    // init: h(-1)=0, q-partials(t=0)=0
    if (bid < 64) {
        for (int u = tid; u < H_; u += 256) {
            g_h[(size_t)bid * H_ + u] = 0.f;
            g_inp[(size_t)bid * KIN_ + 576 + u] = 0.f;
        }
    }
    sv[tid] = v[tid];
    g_qp[bid * 256 + tid] = 0.f;      // 128*256 = 2*B*A exactly
    gbar(ep);

    for (int t = 0; t < T_; t++) {
        // ==== Phase A: cell(t-1) + q-tail + pair-sync + attention(t) ====
        if (t > 0) {
            float gi = g_bias[u0], gf = g_bias[H_ + u0];
            float gg = g_bias[2 * H_ + u0], go = g_bias[3 * H_ + u0];
#pragma unroll
            for (int p = 0; p < 4; p++) {
                const float* pp = g_part + (size_t)p * (B_ * G4_) + b0 * G4_;
                gi += __ldcg(&pp[u0]);
                gf += __ldcg(&pp[H_ + u0]);
                gg += __ldcg(&pp[2 * H_ + u0]);
                go += __ldcg(&pp[3 * H_ + u0]);
            }
            float cn = sigf(gf) * c_reg + sigf(gi) * tanhf(gg);
            float hn = sigf(go) * tanhf(cn);
            c_reg = cn;
            g_h[(size_t)b0 * H_ + u0] = hn;
            g_inp[(size_t)b0 * KIN_ + 576 + u0] = hn;
            g_hist[((size_t)b0 * T_ + (t - 1)) * H_ + u0] = hn;
            h_loc[tid] = hn;
            __syncthreads();
            // q-partial from smem-cached fp16 WqT: a = tid
            {
                float qa = 0.f;
#pragma unroll 8
                for (int j = 0; j < 256; j++)
                    qa += h_loc[j] * __half2float(wq_s[j * 256 + tid]);
                g_qp[(size_t)hf * (B_ * A_) + b0 * A_ + tid] = qa;
            }
            __syncthreads();
            // pair exchange: publish then wait for partner's epoch
            if (tid == 0) {
                __threadfence();
                atomicExch(&g_qflag[bid], (unsigned)t);
                while (ldcg_u(&g_qflag[partner]) < (unsigned)t) __nanosleep(20);
            }
            __syncthreads();
        }
        // attention for step t (both pair CTAs: identical softmax, split ctx)
        {
            const int b = b0, dh = hf;
            sq[tid] = __ldcg(&g_qp[b * A_ + tid])
                    + __ldcg(&g_qp[B_ * A_ + b * A_ + tid]);
            __syncthreads();
            float e = 0.f;
            const __half* kp = g_keysTh + ((size_t)b * A_) * TE_ + tid;
#pragma unroll 8
            for (int a = 0; a < A_; a++)
                e += sv[a] * tanha(sq[a] + __half2float(kp[(size_t)a * TE_]));
            float mx = blk_reduce_max(e, sred);
            float wv = __expf(e - mx);
            float sm = blk_reduce_sum(wv, sred);
            sw[tid] = wv * __fdividef(1.f, sm);
            if (dh == 0 && tid < IN_)
                g_inp[b * KIN_ + tid] = x[((size_t)b * T_ + t) * IN_ + tid];
            __syncthreads();
            const int d4 = tid & 63, th = tid >> 6;
            float4 acc = {0.f, 0.f, 0.f, 0.f};
            const uint2* ebase =
                (const uint2*)(g_encH + (size_t)b * TE_ * H_ + dh * 256) + d4;
#pragma unroll 4
            for (int e2 = th * 64; e2 < th * 64 + 64; e2++) {
                float ww = sw[e2];
                uint2 ev = ebase[(size_t)e2 * (H_ / 4)];
                float2 f01 = __half22float2(*(const __half2*)&ev.x);
                float2 f23 = __half22float2(*(const __half2*)&ev.y);
                acc.x += ww * f01.x; acc.y += ww * f01.y;
                acc.z += ww * f23.x; acc.w += ww * f23.y;
            }
            sctx[tid] = acc;
            __syncthreads();
            if (tid < 64) {
                float4 a0 = sctx[tid],       a1 = sctx[64 + tid];
                float4 a2 = sctx[128 + tid], a3 = sctx[192 + tid];
                float4 o;
                o.x = (a0.x + a1.x) + (a2.x + a3.x);
                o.y = (a0.y + a1.y) + (a2.y + a3.y);
                o.z = (a0.z + a1.z) + (a2.z + a3.z);
                o.w = (a0.w + a1.w) + (a2.w + a3.w);
                *(float4*)&g_inp[b * KIN_ + IN_ + dh * 256 + tid * 4] = o;
            }
        }
        gbar(ep);

        // ==== Phase B: gates GEMM partials (all 128 CTAs) ====
        {
            const int nt = bid >> 2, ks = bid & 3;
            float acc[4][4];
            tile_gemm64<true>(g_inp + ks * 272, KIN_,
                              g_Wp + (size_t)(nt * 64) * KIN_ + ks * 272, KIN_, 17, S, acc);
            const int tm = (tid & 15) << 2, tn = (tid >> 4) << 2;
            float* C = g_part + (size_t)ks * (B_ * G4_);
#pragma unroll
            for (int i = 0; i < 4; i++) {
                float4 o = {acc[i][0], acc[i][1], acc[i][2], acc[i][3]};
                *(float4*)&C[(size_t)(tm + i) * G4_ + nt * 64 + tn] = o;
            }
        }
        gbar(ep);
    }

    // final cell for step T-1 (h_hist[127]); no attention follows
    {
        float gi = g_bias[u0], gf = g_bias[H_ + u0];
        float gg = g_bias[2 * H_ + u0], go = g_bias[3 * H_ + u0];
#pragma unroll
        for (int p = 0; p < 4; p++) {
            const float* pp = g_part + (size_t)p * (B_ * G4_) + b0 * G4_;
            gi += __ldcg(&pp[u0]);
            gf += __ldcg(&pp[H_ + u0]);
            gg += __ldcg(&pp[2 * H_ + u0]);
            go += __ldcg(&pp[3 * H_ + u0]);
        }
        float cn = sigf(gf) * c_reg + sigf(gi) * tanhf(gg);
        float hn = sigf(go) * tanhf(cn);
        g_hist[((size_t)b0 * T_ + (T_ - 1)) * H_ + u0] = hn;
    }
}

// ---------------------------------------------------------------------------
extern "C" void kernel_launch(void* const* d_in, const int* in_sizes, int n_in,
                              void* d_out, int out_size)
{
    const float* x   = (const float*)d_in[0];
    const float* enc = (const float*)d_in[1];
    const float* Wq  = (const float*)d_in[2];
    const float* Wk  = (const float*)d_in[3];
    const float* v   = (const float*)d_in[4];
    const float* Wih = (const float*)d_in[5];
    const float* Whh = (const float*)d_in[6];
    const float* bih = (const float*)d_in[7];
    const float* bhh = (const float*)d_in[8];
    const float* Wfc = (const float*)d_in[9];
    const float* bfc = (const float*)d_in[10];

    float* keys_p = nullptr;
    float* hist_p = nullptr;
    cudaGetSymbolAddress((void**)&keys_p, g_keys);
    cudaGetSymbolAddress((void**)&hist_p, g_hist);

    cudaFuncSetAttribute(persist_kernel,
                         cudaFuncAttributeMaxDynamicSharedMemorySize,
                         WQ_SMEM_BYTES);

    dim3 thr(256);

    reset_kernel<<<1, 256>>>();
    pack_kernel<<<512, thr>>>(Wq, Wih, Whh, bih, bhh, enc);

    // keys[b,e,a] = enc[b,e,:] . W_key[a,:] ; transpose -> fp16 [b][a][e]
    gemm_abt_kernel<<<dim3((B_*TE_)/64, A_/64), thr>>>(enc, Wk, keys_p, A_, H_, nullptr);
    transpose_kernel<<<dim3(TE_/32, A_/32, B_), dim3(32, 8)>>>();

    persist_kernel<<<GRID_, thr, WQ_SMEM_BYTES>>>(x, enc, v);

    // out[b,t,:] = h_hist[b,t,:] @ Wfc^T + bfc
    gemm_abt_kernel<<<dim3((B_*T_)/64, OUT_/64), thr>>>(hist_p, Wfc, (float*)d_out, OUT_, H_, bfc);
}